// round 12
// baseline (speedup 1.0000x reference)
#include <cuda_runtime.h>
#include <cstddef>

typedef unsigned long long u64;

// Scratch (static __device__ — no allocations allowed).
__device__ float g_hA[2097152];   // 512*256*16 (layer1 out, reused by layer3 out)
__device__ float g_hB[1048576];   // 512*128*16 (layer2 out, reused by layer4 out)

// ---------------- packed f32x2 helpers (dual-fp32 pipe) --------------------
__device__ __forceinline__ void fma2(u64& d, u64 a, u64 b) {
    asm("fma.rn.f32x2 %0, %1, %2, %0;" : "+l"(d) : "l"(a), "l"(b));
}
__device__ __forceinline__ u64 add2(u64 a, u64 b) {
    u64 d; asm("add.rn.f32x2 %0, %1, %2;" : "=l"(d) : "l"(a), "l"(b)); return d;
}
__device__ __forceinline__ u64 pack2(float x) {
    u64 d; asm("mov.b64 %0, {%1, %1};" : "=l"(d) : "f"(x)); return d;
}
__device__ __forceinline__ void unpack2(u64 a, float& lo, float& hi) {
    asm("mov.b64 {%0, %1}, %2;" : "=f"(lo), "=f"(hi) : "l"(a));
}

// store one k-quad: log + base, float4 store.
__device__ __forceinline__ void store_quad(float* dst, u64 lo, u64 hi, float base) {
    float x0, x1, x2, x3;
    unpack2(lo, x0, x1);
    unpack2(hi, x2, x3);
    *(float4*)dst = make_float4(__logf(x0) + base, __logf(x1) + base,
                                __logf(x2) + base, __logf(x3) + base);
}

// ---------------------------------------------------------------------------
// One SPN layer, fused normalized weight softmax (R11), m-split over i with
// MS ∈ {1,2,4,8,16} lanes. Per-thread instruction mix is MS-invariant, so
// raising MS multiplies the grid (occupancy) at zero instruction cost:
//   L2: MS=4 (1024 blocks), L3: MS=8 (1024), L4: MS=16 (1024).
// MS=16 (new): G=1, scalar child loads, 4 shfl-reduce rounds (dist 1,2 use
// the register twist u^2/u^4; dist 4,8 plain — xr identical across partners).
// ---------------------------------------------------------------------------
template<int MS, int MINB>
__global__ void __launch_bounds__(128, MINB) layer_kernel(
    const float* __restrict__ hin, const float* __restrict__ Wl,
    float* __restrict__ hout, int F_in)
{
    constexpr int G    = 16 / MS;               // i-values per thread
    constexpr int NSL  = 128 / MS;              // n-slots per block
    constexpr int LG   = (G == 16) ? 4 : (G == 8) ? 3 : (G == 4) ? 2
                                      : (G == 2) ? 1 : 0;
    constexpr int XRM  = (MS < 4 ? MS : 4) - 1; // quad-xor mask
    constexpr int UJ   = (MS <= 2) ? 2 : (MS <= 8) ? 4 : 16;  // j-unroll
    constexpr int REDA = 4096;                  // colmax cross-warp (64 f)
    constexpr int REDB = 4160;                  // colsum cross-warp (64 f)
    constexpr int BR   = 4224;                  // b rows (NSL * 34)

    extern __shared__ float sm[];
    float* Ssm   = sm;                          // 4096 floats (swizzled S)
    float* Brows = sm + BR;

    const int tid  = threadIdx.x;
    const int si   = tid & (MS - 1);
    const int nl   = tid / MS;
    const int f    = blockIdx.x;
    const int F_out = F_in >> 1;
    const int n0   = blockIdx.y * (2 * NSL) + nl;
    const int n1   = n0 + NSL;
    const int xr   = si & XRM;
    const int q    = tid & 3;                   // this thread's k-quad
    const int wid  = tid >> 5;
    const int lane = tid & 31;

    // ---- Fused weight softmax (fully normalized) -----------------------
    float4 wreg[8];
    {
        const float4* Wg = (const float4*)(Wl + (size_t)f * 4096);
        #pragma unroll
        for (int s8 = 0; s8 < 8; s8++) wreg[s8] = Wg[tid + 128 * s8];
    }
    float4 mx4 = wreg[0];
    #pragma unroll
    for (int s8 = 1; s8 < 8; s8++) {
        mx4.x = fmaxf(mx4.x, wreg[s8].x); mx4.y = fmaxf(mx4.y, wreg[s8].y);
        mx4.z = fmaxf(mx4.z, wreg[s8].z); mx4.w = fmaxf(mx4.w, wreg[s8].w);
    }
    #pragma unroll
    for (int off = 4; off < 32; off <<= 1) {
        mx4.x = fmaxf(mx4.x, __shfl_xor_sync(0xffffffffu, mx4.x, off));
        mx4.y = fmaxf(mx4.y, __shfl_xor_sync(0xffffffffu, mx4.y, off));
        mx4.z = fmaxf(mx4.z, __shfl_xor_sync(0xffffffffu, mx4.z, off));
        mx4.w = fmaxf(mx4.w, __shfl_xor_sync(0xffffffffu, mx4.w, off));
    }
    if (lane < 4) *(float4*)(sm + REDA + wid * 16 + q * 4) = mx4;
    __syncthreads();
    {
        mx4 = *(const float4*)(sm + REDA + q * 4);
        #pragma unroll
        for (int w = 1; w < 4; w++) {
            float4 t = *(const float4*)(sm + REDA + w * 16 + q * 4);
            mx4.x = fmaxf(mx4.x, t.x); mx4.y = fmaxf(mx4.y, t.y);
            mx4.z = fmaxf(mx4.z, t.z); mx4.w = fmaxf(mx4.w, t.w);
        }
    }
    float4 sum4 = make_float4(0.f, 0.f, 0.f, 0.f);
    #pragma unroll
    for (int s8 = 0; s8 < 8; s8++) {
        wreg[s8].x = __expf(wreg[s8].x - mx4.x);
        wreg[s8].y = __expf(wreg[s8].y - mx4.y);
        wreg[s8].z = __expf(wreg[s8].z - mx4.z);
        wreg[s8].w = __expf(wreg[s8].w - mx4.w);
        sum4.x += wreg[s8].x; sum4.y += wreg[s8].y;
        sum4.z += wreg[s8].z; sum4.w += wreg[s8].w;
    }
    #pragma unroll
    for (int off = 4; off < 32; off <<= 1) {
        sum4.x += __shfl_xor_sync(0xffffffffu, sum4.x, off);
        sum4.y += __shfl_xor_sync(0xffffffffu, sum4.y, off);
        sum4.z += __shfl_xor_sync(0xffffffffu, sum4.z, off);
        sum4.w += __shfl_xor_sync(0xffffffffu, sum4.w, off);
    }
    if (lane < 4) *(float4*)(sm + REDB + wid * 16 + q * 4) = sum4;
    __syncthreads();
    {
        sum4 = *(const float4*)(sm + REDB + q * 4);
        #pragma unroll
        for (int w = 1; w < 4; w++) {
            float4 t = *(const float4*)(sm + REDB + w * 16 + q * 4);
            sum4.x += t.x; sum4.y += t.y; sum4.z += t.z; sum4.w += t.w;
        }
    }
    const float4 inv4 = make_float4(1.f / sum4.x, 1.f / sum4.y,
                                    1.f / sum4.z, 1.f / sum4.w);
    #pragma unroll
    for (int s8 = 0; s8 < 8; s8++) {
        const int idx = tid + 128 * s8;
        const int m = idx >> 2;
        float4 e = make_float4(wreg[s8].x * inv4.x, wreg[s8].y * inv4.y,
                               wreg[s8].z * inv4.z, wreg[s8].w * inv4.w);
        const int xi = (m >> (4 + LG)) & XRM;
        *(float4*)(Ssm + m * 16 + 4 * (q ^ xi)) = e;
    }

    // ---- Prologue: children -> maxes (shfl across si), exps ------------
    float a0[G], a1[G];
    float base0, base1;
    float* row = Brows + nl * 34;
    {
        float av[G], bv[G];
        const float* h0 = hin + ((size_t)n0 * F_in + 2 * f) * 16 + G * si;
        if constexpr (G >= 4) {
            #pragma unroll
            for (int c = 0; c < G / 4; c++) {
                ((float4*)av)[c] = *(const float4*)(h0 + 4 * c);
                ((float4*)bv)[c] = *(const float4*)(h0 + 16 + 4 * c);
            }
        } else if constexpr (G == 2) {
            ((float2*)av)[0] = *(const float2*)(h0);
            ((float2*)bv)[0] = *(const float2*)(h0 + 16);
        } else {
            av[0] = h0[0];
            bv[0] = h0[16];
        }
        float l = av[0], r = bv[0];
        #pragma unroll
        for (int d = 1; d < G; d++) { l = fmaxf(l, av[d]); r = fmaxf(r, bv[d]); }
        #pragma unroll
        for (int rr = 1; rr < MS; rr <<= 1) {
            l = fmaxf(l, __shfl_xor_sync(0xffffffffu, l, rr));
            r = fmaxf(r, __shfl_xor_sync(0xffffffffu, r, rr));
        }
        #pragma unroll
        for (int d = 0; d < G; d++) {
            a0[d] = __expf(av[d] - l);
            row[2 * (G * si + d)] = __expf(bv[d] - r);
        }
        base0 = l + r;
    }
    {
        float av[G], bv[G];
        const float* h1 = hin + ((size_t)n1 * F_in + 2 * f) * 16 + G * si;
        if constexpr (G >= 4) {
            #pragma unroll
            for (int c = 0; c < G / 4; c++) {
                ((float4*)av)[c] = *(const float4*)(h1 + 4 * c);
                ((float4*)bv)[c] = *(const float4*)(h1 + 16 + 4 * c);
            }
        } else if constexpr (G == 2) {
            ((float2*)av)[0] = *(const float2*)(h1);
            ((float2*)bv)[0] = *(const float2*)(h1 + 16);
        } else {
            av[0] = h1[0];
            bv[0] = h1[16];
        }
        float l = av[0], r = bv[0];
        #pragma unroll
        for (int d = 1; d < G; d++) { l = fmaxf(l, av[d]); r = fmaxf(r, bv[d]); }
        #pragma unroll
        for (int rr = 1; rr < MS; rr <<= 1) {
            l = fmaxf(l, __shfl_xor_sync(0xffffffffu, l, rr));
            r = fmaxf(r, __shfl_xor_sync(0xffffffffu, r, rr));
        }
        #pragma unroll
        for (int d = 0; d < G; d++) {
            a1[d] = __expf(av[d] - l);
            row[2 * (G * si + d) + 1] = __expf(bv[d] - r);
        }
        base1 = l + r;
    }
    __syncthreads();   // Ssm and b-rows ready

    // ---- Mainloop. acc[2q+t] = logical quad (q^xr), halves t (k-pairs) --
    u64 acc0[8], acc1[8];
    #pragma unroll
    for (int u = 0; u < 8; u++) { acc0[u] = 0ull; acc1[u] = 0ull; }

    const float* pq0 = Ssm + si * (G * 256) + 4 * (0 ^ xr);
    const float* pq1 = Ssm + si * (G * 256) + 4 * (1 ^ xr);
    const float* pq2 = Ssm + si * (G * 256) + 4 * (2 ^ xr);
    const float* pq3 = Ssm + si * (G * 256) + 4 * (3 ^ xr);
    const u64* rowq = (const u64*)row;

    #pragma unroll UJ
    for (int j = 0; j < 16; j++) {
        float b0, b1;
        unpack2(rowq[j], b0, b1);
        const int jo = j * 16;
        #pragma unroll
        for (int d = 0; d < G; d++) {
            const int o = d * 256 + jo;
            const u64 p0 = pack2(a0[d] * b0);
            const u64 p1 = pack2(a1[d] * b1);
            ulonglong2 w;
        w = *(const ulonglong2*)(pq0 + o);
            fma2(acc0[0], p0, w.x); fma2(acc0[1], p0, w.y);
            fma2(acc1[0], p1, w.x); fma2(acc1[1], p1, w.y);
            w = *(const ulonglong2*)(pq1 + o);
            fma2(acc0[2], p0, w.x); fma2(acc0[3], p0, w.y);
            fma2(acc1[2], p1, w.x); fma2(acc1[3], p1, w.y);
            w = *(const ulonglong2*)(pq2 + o);
            fma2(acc0[4], p0, w.x); fma2(acc0[5], p0, w.y);
            fma2(acc1[4], p1, w.x); fma2(acc1[5], p1, w.y);
            w = *(const ulonglong2*)(pq3 + o);
            fma2(acc0[6], p0, w.x); fma2(acc0[7], p0, w.y);
            fma2(acc1[6], p1, w.x); fma2(acc1[7], p1, w.y);
        }
    }

    // ---- Reduce across si lanes: dist 1,2 twisted; dist 4,8 plain -------
    if constexpr (MS >= 2) {
        u64 t0[8], t1[8];
        #pragma unroll
        for (int u = 0; u < 8; u++) {
            t0[u] = __shfl_xor_sync(0xffffffffu, acc0[u ^ 2], 1);
            t1[u] = __shfl_xor_sync(0xffffffffu, acc1[u ^ 2], 1);
        }
        #pragma unroll
        for (int u = 0; u < 8; u++) { acc0[u] = add2(acc0[u], t0[u]); acc1[u] = add2(acc1[u], t1[u]); }
    }
    if constexpr (MS >= 4) {
        u64 t0[8], t1[8];
        #pragma unroll
        for (int u = 0; u < 8; u++) {
            t0[u] = __shfl_xor_sync(0xffffffffu, acc0[u ^ 4], 2);
            t1[u] = __shfl_xor_sync(0xffffffffu, acc1[u ^ 4], 2);
        }
        #pragma unroll
        for (int u = 0; u < 8; u++) { acc0[u] = add2(acc0[u], t0[u]); acc1[u] = add2(acc1[u], t1[u]); }
    }
    if constexpr (MS >= 8) {
        u64 t0[8], t1[8];
        #pragma unroll
        for (int u = 0; u < 8; u++) {
            t0[u] = __shfl_xor_sync(0xffffffffu, acc0[u], 4);
            t1[u] = __shfl_xor_sync(0xffffffffu, acc1[u], 4);
        }
        #pragma unroll
        for (int u = 0; u < 8; u++) { acc0[u] = add2(acc0[u], t0[u]); acc1[u] = add2(acc1[u], t1[u]); }
    }
    if constexpr (MS >= 16) {
        u64 t0[8], t1[8];
        #pragma unroll
        for (int u = 0; u < 8; u++) {
            t0[u] = __shfl_xor_sync(0xffffffffu, acc0[u], 8);
            t1[u] = __shfl_xor_sync(0xffffffffu, acc1[u], 8);
        }
        #pragma unroll
        for (int u = 0; u < 8; u++) { acc0[u] = add2(acc0[u], t0[u]); acc1[u] = add2(acc1[u], t1[u]); }
    }

    // ---- Store -----------------------------------------------------------
    float* o0p = hout + ((size_t)n0 * F_out + f) * 16;
    float* o1p = hout + ((size_t)n1 * F_out + f) * 16;
    if constexpr (MS == 1) {
        #pragma unroll
        for (int qq = 0; qq < 4; qq++) {
            store_quad(o0p + 4 * qq, acc0[2 * qq], acc0[2 * qq + 1], base0);
            store_quad(o1p + 4 * qq, acc1[2 * qq], acc1[2 * qq + 1], base1);
        }
    } else if constexpr (MS == 2) {
        const int ka = si ? 12 : 0, kb = si ? 8 : 4;
        u64 A0 = si ? acc0[4] : acc0[0], A1 = si ? acc0[5] : acc0[1];
        u64 B0 = si ? acc0[6] : acc0[2], B1 = si ? acc0[7] : acc0[3];
        store_quad(o0p + ka, A0, A1, base0);
        store_quad(o0p + kb, B0, B1, base0);
        u64 C0 = si ? acc1[4] : acc1[0], C1 = si ? acc1[5] : acc1[1];
        u64 D0 = si ? acc1[6] : acc1[2], D1 = si ? acc1[7] : acc1[3];
        store_quad(o1p + ka, C0, C1, base1);
        store_quad(o1p + kb, D0, D1, base1);
    } else if constexpr (MS == 4) {
        store_quad(o0p + 4 * si, acc0[0], acc0[1], base0);
        store_quad(o1p + 4 * si, acc1[0], acc1[1], base1);
    } else { // MS >= 8: lanes si<4 carry logical quad (si&3)
        if (si < 4) {
            store_quad(o0p + 4 * si, acc0[0], acc0[1], base0);
            store_quad(o1p + 4 * si, acc1[0], acc1[1], base1);
        }
    }
}

// ---------------------------------------------------------------------------
// Root. Block per n (512 blocks, 32 threads), warp-shfl reduce.
// ---------------------------------------------------------------------------
__global__ void __launch_bounds__(32) root_kernel(
    const float* __restrict__ h4, const float* __restrict__ Wroot,
    float* __restrict__ out)
{
    const int n = blockIdx.x;
    const int t = threadIdx.x;
    const float4* hp = (const float4*)(h4 + (size_t)n * 512);

    float4 a = make_float4(0.f, 0.f, 0.f, 0.f);
    #pragma unroll
    for (int r = 0; r < 4; r++) {
        float4 q = hp[t + 32 * r];
        a.x += q.x; a.y += q.y; a.z += q.z; a.w += q.w;
    }
    #pragma unroll
    for (int st = 4; st <= 16; st <<= 1) {
        a.x += __shfl_xor_sync(0xffffffffu, a.x, st);
        a.y += __shfl_xor_sync(0xffffffffu, a.y, st);
        a.z += __shfl_xor_sync(0xffffffffu, a.z, st);
        a.w += __shfl_xor_sync(0xffffffffu, a.w, st);
    }
    __shared__ float sred[16];
    if (t < 4) { sred[4*t] = a.x; sred[4*t+1] = a.y; sred[4*t+2] = a.z; sred[4*t+3] = a.w; }
    __syncwarp();

    if (t == 0) {
        float w[16];
        #pragma unroll
        for (int k = 0; k < 16; k++) w[k] = Wroot[k];
        float wm = w[0];
        #pragma unroll
        for (int k = 1; k < 16; k++) wm = fmaxf(wm, w[k]);
        float Z = 0.f;
        #pragma unroll
        for (int k = 0; k < 16; k++) Z += __expf(w[k] - wm);
        const float lz = __logf(Z) + wm;

        float tv[16];
        float tm = -1e30f;
        #pragma unroll
        for (int k = 0; k < 16; k++) {
            tv[k] = sred[k] + w[k] - lz;
            tm = fmaxf(tm, tv[k]);
        }
        float ss = 0.f;
        #pragma unroll
        for (int k = 0; k < 16; k++) ss += __expf(tv[k] - tm);
        out[n] = __logf(ss) + tm;
    }
}

// ---------------------------------------------------------------------------
extern "C" void kernel_launch(void* const* d_in, const int* in_sizes, int n_in,
                              void* d_out, int out_size)
{
    const float* x  = (const float*)d_in[0];
    const float* W1 = (const float*)d_in[1];
    const float* W2 = (const float*)d_in[2];
    const float* W3 = (const float*)d_in[3];
    const float* W4 = (const float*)d_in[4];
    const float* Wr = (const float*)d_in[5];
    float* out = (float*)d_out;

    float *hA, *hB;
    cudaGetSymbolAddress((void**)&hA, g_hA);
    cudaGetSymbolAddress((void**)&hB, g_hB);

    // smem = (4224 + NSL*34) floats.
    const size_t sm1  = (4224 + 128 * 34) * 4;  // MS=1 : 34304
    const size_t sm4  = (4224 +  32 * 34) * 4;  // MS=4 : 21248
    const size_t sm8  = (4224 +  16 * 34) * 4;  // MS=8 : 19072
    const size_t sm16 = (4224 +   8 * 34) * 4;  // MS=16: 17984

    // L1 at its fma floor (512 blocks). L2-L4 promoted to 1024 blocks via
    // MS (instruction-mix invariant) to double occupancy.
    layer_kernel<1, 2><<<dim3(256, 2),  128, sm1 >>>(x,  W1, hA, 512);
    layer_kernel<4, 6><<<dim3(128, 8),  128, sm4 >>>(hA, W2, hB, 256);
    layer_kernel<8, 7><<<dim3(64, 16),  128, sm8 >>>(hB, W3, hA, 128);
    layer_kernel<16,7><<<dim3(32, 32),  128, sm16>>>(hA, W4, hB, 64);

    root_kernel<<<512, 32>>>(hB, Wr, out);
}

// round 14
// speedup vs baseline: 1.0212x; 1.0212x over previous
#include <cuda_runtime.h>
#include <cstddef>

typedef unsigned long long u64;

// Scratch (static __device__ — no allocations allowed).
__device__ float g_hA[2097152];   // L1 out (512*256*16); later L4 out (512*32*16)
__device__ float g_hB[1048576];   // L2 out (512*128*16)

// ---------------- packed f32x2 helpers (dual-fp32 pipe) --------------------
__device__ __forceinline__ void fma2(u64& d, u64 a, u64 b) {
    asm("fma.rn.f32x2 %0, %1, %2, %0;" : "+l"(d) : "l"(a), "l"(b));
}
__device__ __forceinline__ u64 add2(u64 a, u64 b) {
    u64 d; asm("add.rn.f32x2 %0, %1, %2;" : "=l"(d) : "l"(a), "l"(b)); return d;
}
__device__ __forceinline__ u64 pack2(float x) {
    u64 d; asm("mov.b64 %0, {%1, %1};" : "=l"(d) : "f"(x)); return d;
}
__device__ __forceinline__ void unpack2(u64 a, float& lo, float& hi) {
    asm("mov.b64 {%0, %1}, %2;" : "=f"(lo), "=f"(hi) : "l"(a));
}

// store one k-quad: log + base, float4 store.
__device__ __forceinline__ void store_quad(float* dst, u64 lo, u64 hi, float base) {
    float x0, x1, x2, x3;
    unpack2(lo, x0, x1);
    unpack2(hi, x2, x3);
    *(float4*)dst = make_float4(__logf(x0) + base, __logf(x1) + base,
                                __logf(x2) + base, __logf(x3) + base);
}

// ---------------------------------------------------------------------------
// Layer kernel — VERBATIM R11 (best passing: 82.5us). Used for L1 (MS=1) and
// L2 (MS=2). Fused normalized weight softmax; m-split over i; NT=2.
// ---------------------------------------------------------------------------
template<int MS>
__global__ void __launch_bounds__(128) layer_kernel(
    const float* __restrict__ hin, const float* __restrict__ Wl,
    float* __restrict__ hout, int F_in)
{
    constexpr int G    = 16 / MS;
    constexpr int NSL  = 128 / MS;
    constexpr int LG   = (G == 16) ? 4 : (G == 8) ? 3 : (G == 4) ? 2 : 1;
    constexpr int XRM  = (MS < 4 ? MS : 4) - 1;
    constexpr int UJ   = (MS <= 2) ? 2 : 4;
    constexpr int REDA = 4096;
    constexpr int REDB = 4160;
    constexpr int BR   = 4224;

    extern __shared__ float sm[];
    float* Ssm   = sm;
    float* Brows = sm + BR;

    const int tid  = threadIdx.x;
    const int si   = tid & (MS - 1);
    const int nl   = tid / MS;
    const int f    = blockIdx.x;
    const int F_out = F_in >> 1;
    const int n0   = blockIdx.y * (2 * NSL) + nl;
    const int n1   = n0 + NSL;
    const int xr   = si & XRM;
    const int q    = tid & 3;
    const int wid  = tid >> 5;
    const int lane = tid & 31;

    // ---- Fused weight softmax (fully normalized) -----------------------
    float4 wreg[8];
    {
        const float4* Wg = (const float4*)(Wl + (size_t)f * 4096);
        #pragma unroll
        for (int s8 = 0; s8 < 8; s8++) wreg[s8] = Wg[tid + 128 * s8];
    }
    float4 mx4 = wreg[0];
    #pragma unroll
    for (int s8 = 1; s8 < 8; s8++) {
        mx4.x = fmaxf(mx4.x, wreg[s8].x); mx4.y = fmaxf(mx4.y, wreg[s8].y);
        mx4.z = fmaxf(mx4.z, wreg[s8].z); mx4.w = fmaxf(mx4.w, wreg[s8].w);
    }
    #pragma unroll
    for (int off = 4; off < 32; off <<= 1) {
        mx4.x = fmaxf(mx4.x, __shfl_xor_sync(0xffffffffu, mx4.x, off));
        mx4.y = fmaxf(mx4.y, __shfl_xor_sync(0xffffffffu, mx4.y, off));
        mx4.z = fmaxf(mx4.z, __shfl_xor_sync(0xffffffffu, mx4.z, off));
        mx4.w = fmaxf(mx4.w, __shfl_xor_sync(0xffffffffu, mx4.w, off));
    }
    if (lane < 4) *(float4*)(sm + REDA + wid * 16 + q * 4) = mx4;
    __syncthreads();
    {
        mx4 = *(const float4*)(sm + REDA + q * 4);
        #pragma unroll
        for (int w = 1; w < 4; w++) {
            float4 t = *(const float4*)(sm + REDA + w * 16 + q * 4);
            mx4.x = fmaxf(mx4.x, t.x); mx4.y = fmaxf(mx4.y, t.y);
            mx4.z = fmaxf(mx4.z, t.z); mx4.w = fmaxf(mx4.w, t.w);
        }
    }
    float4 sum4 = make_float4(0.f, 0.f, 0.f, 0.f);
    #pragma unroll
    for (int s8 = 0; s8 < 8; s8++) {
        wreg[s8].x = __expf(wreg[s8].x - mx4.x);
        wreg[s8].y = __expf(wreg[s8].y - mx4.y);
        wreg[s8].z = __expf(wreg[s8].z - mx4.z);
        wreg[s8].w = __expf(wreg[s8].w - mx4.w);
        sum4.x += wreg[s8].x; sum4.y += wreg[s8].y;
        sum4.z += wreg[s8].z; sum4.w += wreg[s8].w;
    }
    #pragma unroll
    for (int off = 4; off < 32; off <<= 1) {
        sum4.x += __shfl_xor_sync(0xffffffffu, sum4.x, off);
        sum4.y += __shfl_xor_sync(0xffffffffu, sum4.y, off);
        sum4.z += __shfl_xor_sync(0xffffffffu, sum4.z, off);
        sum4.w += __shfl_xor_sync(0xffffffffu, sum4.w, off);
    }
    if (lane < 4) *(float4*)(sm + REDB + wid * 16 + q * 4) = sum4;
    __syncthreads();
    {
        sum4 = *(const float4*)(sm + REDB + q * 4);
        #pragma unroll
        for (int w = 1; w < 4; w++) {
            float4 t = *(const float4*)(sm + REDB + w * 16 + q * 4);
            sum4.x += t.x; sum4.y += t.y; sum4.z += t.z; sum4.w += t.w;
        }
    }
    const float4 inv4 = make_float4(1.f / sum4.x, 1.f / sum4.y,
                                    1.f / sum4.z, 1.f / sum4.w);
    #pragma unroll
    for (int s8 = 0; s8 < 8; s8++) {
        const int idx = tid + 128 * s8;
        const int m = idx >> 2;
        float4 e = make_float4(wreg[s8].x * inv4.x, wreg[s8].y * inv4.y,
                               wreg[s8].z * inv4.z, wreg[s8].w * inv4.w);
        const int xi = (m >> (4 + LG)) & XRM;
        *(float4*)(Ssm + m * 16 + 4 * (q ^ xi)) = e;
    }

    // ---- Prologue -------------------------------------------------------
    float a0[G], a1[G];
    float base0, base1;
    float* row = Brows + nl * 34;
    {
        float av[G], bv[G];
        const float* h0 = hin + ((size_t)n0 * F_in + 2 * f) * 16 + G * si;
        if constexpr (G >= 4) {
            #pragma unroll
            for (int c = 0; c < G / 4; c++) {
                ((float4*)av)[c] = *(const float4*)(h0 + 4 * c);
                ((float4*)bv)[c] = *(const float4*)(h0 + 16 + 4 * c);
            }
        } else {
            ((float2*)av)[0] = *(const float2*)(h0);
            ((float2*)bv)[0] = *(const float2*)(h0 + 16);
        }
        float l = av[0], r = bv[0];
        #pragma unroll
        for (int d = 1; d < G; d++) { l = fmaxf(l, av[d]); r = fmaxf(r, bv[d]); }
        #pragma unroll
        for (int rr = 1; rr < MS; rr <<= 1) {
            l = fmaxf(l, __shfl_xor_sync(0xffffffffu, l, rr));
            r = fmaxf(r, __shfl_xor_sync(0xffffffffu, r, rr));
        }
        #pragma unroll
        for (int d = 0; d < G; d++) {
            a0[d] = __expf(av[d] - l);
            row[2 * (G * si + d)] = __expf(bv[d] - r);
        }
        base0 = l + r;
    }
    {
        float av[G], bv[G];
        const float* h1 = hin + ((size_t)n1 * F_in + 2 * f) * 16 + G * si;
        if constexpr (G >= 4) {
            #pragma unroll
            for (int c = 0; c < G / 4; c++) {
                ((float4*)av)[c] = *(const float4*)(h1 + 4 * c);
                ((float4*)bv)[c] = *(const float4*)(h1 + 16 + 4 * c);
            }
        } else {
            ((float2*)av)[0] = *(const float2*)(h1);
            ((float2*)bv)[0] = *(const float2*)(h1 + 16);
        }
        float l = av[0], r = bv[0];
        #pragma unroll
        for (int d = 1; d < G; d++) { l = fmaxf(l, av[d]); r = fmaxf(r, bv[d]); }
        #pragma unroll
        for (int rr = 1; rr < MS; rr <<= 1) {
            l = fmaxf(l, __shfl_xor_sync(0xffffffffu, l, rr));
            r = fmaxf(r, __shfl_xor_sync(0xffffffffu, r, rr));
        }
        #pragma unroll
        for (int d = 0; d < G; d++) {
            a1[d] = __expf(av[d] - l);
            row[2 * (G * si + d) + 1] = __expf(bv[d] - r);
        }
        base1 = l + r;
    }
    __syncthreads();

    // ---- Mainloop -------------------------------------------------------
    u64 acc0[8], acc1[8];
    #pragma unroll
    for (int u = 0; u < 8; u++) { acc0[u] = 0ull; acc1[u] = 0ull; }

    const float* pq0 = Ssm + si * (G * 256) + 4 * (0 ^ xr);
    const float* pq1 = Ssm + si * (G * 256) + 4 * (1 ^ xr);
    const float* pq2 = Ssm + si * (G * 256) + 4 * (2 ^ xr);
    const float* pq3 = Ssm + si * (G * 256) + 4 * (3 ^ xr);
    const u64* rowq = (const u64*)row;

    #pragma unroll UJ
    for (int j = 0; j < 16; j++) {
        float b0, b1;
        unpack2(rowq[j], b0, b1);
        const int jo = j * 16;
        #pragma unroll
        for (int d = 0; d < G; d++) {
            const int o = d * 256 + jo;
            const u64 p0 = pack2(a0[d] * b0);
            const u64 p1 = pack2(a1[d] * b1);
            ulonglong2 w;
            w = *(const ulonglong2*)(pq0 + o);
            fma2(acc0[0], p0, w.x); fma2(acc0[1], p0, w.y);
            fma2(acc1[0], p1, w.x); fma2(acc1[1], p1, w.y);
            w = *(const ulonglong2*)(pq1 + o);
            fma2(acc0[2], p0, w.x); fma2(acc0[3], p0, w.y);
            fma2(acc1[2], p1, w.x); fma2(acc1[3], p1, w.y);
            w = *(const ulonglong2*)(pq2 + o);
            fma2(acc0[4], p0, w.x); fma2(acc0[5], p0, w.y);
            fma2(acc1[4], p1, w.x); fma2(acc1[5], p1, w.y);
            w = *(const ulonglong2*)(pq3 + o);
            fma2(acc0[6], p0, w.x); fma2(acc0[7], p0, w.y);
            fma2(acc1[6], p1, w.x); fma2(acc1[7], p1, w.y);
        }
    }

    // ---- Reduce across si lanes -----------------------------------------
    if constexpr (MS >= 2) {
        u64 t0[8], t1[8];
        #pragma unroll
        for (int u = 0; u < 8; u++) {
            t0[u] = __shfl_xor_sync(0xffffffffu, acc0[u ^ 2], 1);
            t1[u] = __shfl_xor_sync(0xffffffffu, acc1[u ^ 2], 1);
        }
        #pragma unroll
        for (int u = 0; u < 8; u++) { acc0[u] = add2(acc0[u], t0[u]); acc1[u] = add2(acc1[u], t1[u]); }
    }

    // ---- Store -----------------------------------------------------------
    float* o0p = hout + ((size_t)n0 * F_out + f) * 16;
    float* o1p = hout + ((size_t)n1 * F_out + f) * 16;
    if constexpr (MS == 1) {
        #pragma unroll
        for (int qq = 0; qq < 4; qq++) {
            store_quad(o0p + 4 * qq, acc0[2 * qq], acc0[2 * qq + 1], base0);
            store_quad(o1p + 4 * qq, acc1[2 * qq], acc1[2 * qq + 1], base1);
        }
    } else { // MS == 2
        const int ka = si ? 12 : 0, kb = si ? 8 : 4;
        u64 A0 = si ? acc0[4] : acc0[0], A1 = si ? acc0[5] : acc0[1];
        u64 B0 = si ? acc0[6] : acc0[2], B1 = si ? acc0[7] : acc0[3];
        store_quad(o0p + ka, A0, A1, base0);
        store_quad(o0p + kb, B0, B1, base0);
        u64 C0 = si ? acc1[4] : acc1[0], C1 = si ? acc1[5] : acc1[1];
        u64 D0 = si ? acc1[6] : acc1[2], D1 = si ? acc1[7] : acc1[3];
        store_quad(o1p + ka, C0, C1, base1);
        store_quad(o1p + kb, D0, D1, base1);
    }
}

// ---------------------------------------------------------------------------
// FUSED L3+L4 kernel. Block = (f4, 32-n tile), grid (32,16) = 512 blocks.
// Three phases, each the verbatim R11 MS=8/NT=2 machinery (G=2, NSL=16):
//   p=0: L3 for f3=2*f4   (input hB global, F=128) -> smem O3[0]
//   p=1: L3 for f3=2*f4+1 -> smem O3[1]
//   p=2: L4 for f4 (children read from O3 via LDS) -> global hout
// O3STR = 20 (multiple of 4) keeps every float4 store 16B-aligned — the
// R13 crash was O3STR=18 making odd rows misaligned.
// ---------------------------------------------------------------------------
__global__ void __launch_bounds__(128) l34_kernel(
    const float* __restrict__ hin, const float* __restrict__ W3,
    const float* __restrict__ W4, float* __restrict__ hout)
{
    constexpr int LG    = 1;        // G = 2
    constexpr int XRM   = 3;        // MS = 8
    constexpr int REDA  = 4096;
    constexpr int REDB  = 4160;
    constexpr int BR    = 4224;     // Brows: 16 rows * 34 = 544 floats
    constexpr int O3OFF = BR + 544; // O3: [2][32][20] = 1280 floats
    constexpr int O3STR = 20;       // multiple of 4 -> aligned float4 rows
    constexpr int O3P   = 32 * O3STR;

    extern __shared__ float sm[];
    float* Ssm   = sm;
    float* Brows = sm + BR;
    float* O3    = sm + O3OFF;

    const int tid   = threadIdx.x;
    const int si    = tid & 7;
    const int nl    = tid >> 3;          // 0..15
    const int f4    = blockIdx.x;
    const int nbase = blockIdx.y * 32;
    const int xr    = si & XRM;
    const int q     = tid & 3;
    const int wid   = tid >> 5;
    const int lane  = tid & 31;

    #pragma unroll 1
    for (int p = 0; p < 3; p++) {
        const float* Wsl = (p < 2) ? (W3 + (size_t)(2 * f4 + p) * 4096)
                                   : (W4 + (size_t)f4 * 4096);

        // ---- weight softmax preamble (verbatim R11) ---------------------
        float4 wreg[8];
        {
            const float4* Wg = (const float4*)Wsl;
            #pragma unroll
            for (int s8 = 0; s8 < 8; s8++) wreg[s8] = Wg[tid + 128 * s8];
        }
        float4 mx4 = wreg[0];
        #pragma unroll
        for (int s8 = 1; s8 < 8; s8++) {
            mx4.x = fmaxf(mx4.x, wreg[s8].x); mx4.y = fmaxf(mx4.y, wreg[s8].y);
            mx4.z = fmaxf(mx4.z, wreg[s8].z); mx4.w = fmaxf(mx4.w, wreg[s8].w);
        }
        #pragma unroll
        for (int off = 4; off < 32; off <<= 1) {
            mx4.x = fmaxf(mx4.x, __shfl_xor_sync(0xffffffffu, mx4.x, off));
            mx4.y = fmaxf(mx4.y, __shfl_xor_sync(0xffffffffu, mx4.y, off));
            mx4.z = fmaxf(mx4.z, __shfl_xor_sync(0xffffffffu, mx4.z, off));
            mx4.w = fmaxf(mx4.w, __shfl_xor_sync(0xffffffffu, mx4.w, off));
        }
        if (lane < 4) *(float4*)(sm + REDA + wid * 16 + q * 4) = mx4;
        __syncthreads();
        {
            mx4 = *(const float4*)(sm + REDA + q * 4);
            #pragma unroll
            for (int w = 1; w < 4; w++) {
                float4 t = *(const float4*)(sm + REDA + w * 16 + q * 4);
                mx4.x = fmaxf(mx4.x, t.x); mx4.y = fmaxf(mx4.y, t.y);
                mx4.z = fmaxf(mx4.z, t.z); mx4.w = fmaxf(mx4.w, t.w);
            }
        }
        float4 sum4 = make_float4(0.f, 0.f, 0.f, 0.f);
        #pragma unroll
        for (int s8 = 0; s8 < 8; s8++) {
            wreg[s8].x = __expf(wreg[s8].x - mx4.x);
            wreg[s8].y = __expf(wreg[s8].y - mx4.y);
            wreg[s8].z = __expf(wreg[s8].z - mx4.z);
            wreg[s8].w = __expf(wreg[s8].w - mx4.w);
            sum4.x += wreg[s8].x; sum4.y += wreg[s8].y;
            sum4.z += wreg[s8].z; sum4.w += wreg[s8].w;
        }
        #pragma unroll
        for (int off = 4; off < 32; off <<= 1) {
            sum4.x += __shfl_xor_sync(0xffffffffu, sum4.x, off);
            sum4.y += __shfl_xor_sync(0xffffffffu, sum4.y, off);
            sum4.z += __shfl_xor_sync(0xffffffffu, sum4.z, off);
            sum4.w += __shfl_xor_sync(0xffffffffu, sum4.w, off);
        }
        if (lane < 4) *(float4*)(sm + REDB + wid * 16 + q * 4) = sum4;
        __syncthreads();
        {
            sum4 = *(const float4*)(sm + REDB + q * 4);
            #pragma unroll
            for (int w = 1; w < 4; w++) {
                float4 t = *(const float4*)(sm + REDB + w * 16 + q * 4);
                sum4.x += t.x; sum4.y += t.y; sum4.z += t.z; sum4.w += t.w;
            }
        }
        const float4 inv4 = make_float4(1.f / sum4.x, 1.f / sum4.y,
                                        1.f / sum4.z, 1.f / sum4.w);
        #pragma unroll
        for (int s8 = 0; s8 < 8; s8++) {
            const int idx = tid + 128 * s8;
            const int m = idx >> 2;
            float4 e = make_float4(wreg[s8].x * inv4.x, wreg[s8].y * inv4.y,
                                   wreg[s8].z * inv4.z, wreg[s8].w * inv4.w);
            const int xi = (m >> (4 + LG)) & XRM;
            *(float4*)(Ssm + m * 16 + 4 * (q ^ xi)) = e;
        }

        // ---- prologue: two samples (nl, nl+16) --------------------------
        float a0[2], a1[2];
        float base0 = 0.f, base1 = 0.f;
        float* row = Brows + nl * 34;
        #pragma unroll
        for (int s2 = 0; s2 < 2; s2++) {
            const int nloc = nl + s2 * 16;
            float av[2], bv[2];
            if (p < 2) {
                const float* h = hin +
                    ((size_t)(nbase + nloc) * 128 + (4 * f4 + 2 * p)) * 16 + 2 * si;
                ((float2*)av)[0] = *(const float2*)(h);
                ((float2*)bv)[0] = *(const float2*)(h + 16);
            } else {
                ((float2*)av)[0] = *(const float2*)(O3 + 0 * O3P + nloc * O3STR + 2 * si);
                ((float2*)bv)[0] = *(const float2*)(O3 + 1 * O3P + nloc * O3STR + 2 * si);
            }
            float l = fmaxf(av[0], av[1]);
            float r = fmaxf(bv[0], bv[1]);
            #pragma unroll
            for (int rr = 1; rr < 8; rr <<= 1) {
                l = fmaxf(l, __shfl_xor_sync(0xffffffffu, l, rr));
                r = fmaxf(r, __shfl_xor_sync(0xffffffffu, r, rr));
            }
            if (s2 == 0) {
                a0[0] = __expf(av[0] - l); a0[1] = __expf(av[1] - l);
                row[2 * (2 * si + 0)] = __expf(bv[0] - r);
                row[2 * (2 * si + 1)] = __expf(bv[1] - r);
                base0 = l + r;
            } else {
                a1[0] = __expf(av[0] - l); a1[1] = __expf(av[1] - l);
                row[2 * (2 * si + 0) + 1] = __expf(bv[0] - r);
                row[2 * (2 * si + 1) + 1] = __expf(bv[1] - r);
                base1 = l + r;
            }
        }
        __syncthreads();

        // ---- mainloop (verbatim MS=8, G=2) ------------------------------
        u64 acc0[8], acc1[8];
        #pragma unroll
        for (int u = 0; u < 8; u++) { acc0[u] = 0ull; acc1[u] = 0ull; }

        const float* pq0 = Ssm + si * 512 + 4 * (0 ^ xr);
        const float* pq1 = Ssm + si * 512 + 4 * (1 ^ xr);
        const float* pq2 = Ssm + si * 512 + 4 * (2 ^ xr);
        const float* pq3 = Ssm + si * 512 + 4 * (3 ^ xr);
        const u64* rowq = (const u64*)row;

        #pragma unroll 4
        for (int j = 0; j < 16; j++) {
            float b0, b1;
            unpack2(rowq[j], b0, b1);
            const int jo = j * 16;
            #pragma unroll
            for (int d = 0; d < 2; d++) {
                const int o = d * 256 + jo;
                const u64 p0 = pack2(a0[d] * b0);
                const u64 p1 = pack2(a1[d] * b1);
                ulonglong2 w;
                w = *(const ulonglong2*)(pq0 + o);
                fma2(acc0[0], p0, w.x); fma2(acc0[1], p0, w.y);
                fma2(acc1[0], p1, w.x); fma2(acc1[1], p1, w.y);
                w = *(const ulonglong2*)(pq1 + o);
                fma2(acc0[2], p0, w.x); fma2(acc0[3], p0, w.y);
                fma2(acc1[2], p1, w.x); fma2(acc1[3], p1, w.y);
                w = *(const ulonglong2*)(pq2 + o);
                fma2(acc0[4], p0, w.x); fma2(acc0[5], p0, w.y);
                fma2(acc1[4], p1, w.x); fma2(acc1[5], p1, w.y);
                w = *(const ulonglong2*)(pq3 + o);
                fma2(acc0[6], p0, w.x); fma2(acc0[7], p0, w.y);
                fma2(acc1[6], p1, w.x); fma2(acc1[7], p1, w.y);
            }
        }

        // ---- reduce across 8 si-lanes (verbatim MS=8) -------------------
        {
            u64 t0[8], t1[8];
            #pragma unroll
            for (int u = 0; u < 8; u++) {
                t0[u] = __shfl_xor_sync(0xffffffffu, acc0[u ^ 2], 1);
                t1[u] = __shfl_xor_sync(0xffffffffu, acc1[u ^ 2], 1);
            }
            #pragma unroll
            for (int u = 0; u < 8; u++) { acc0[u] = add2(acc0[u], t0[u]); acc1[u] = add2(acc1[u], t1[u]); }
        }
        {
            u64 t0[8], t1[8];
            #pragma unroll
            for (int u = 0; u < 8; u++) {
                t0[u] = __shfl_xor_sync(0xffffffffu, acc0[u ^ 4], 2);
                t1[u] = __shfl_xor_sync(0xffffffffu, acc1[u ^ 4], 2);
            }
            #pragma unroll
            for (int u = 0; u < 8; u++) { acc0[u] = add2(acc0[u], t0[u]); acc1[u] = add2(acc1[u], t1[u]); }
        }
        {
            u64 t0[8], t1[8];
            #pragma unroll
            for (int u = 0; u < 8; u++) {
                t0[u] = __shfl_xor_sync(0xffffffffu, acc0[u], 4);
                t1[u] = __shfl_xor_sync(0xffffffffu, acc1[u], 4);
            }
            #pragma unroll
            for (int u = 0; u < 8; u++) { acc0[u] = add2(acc0[u], t0[u]); acc1[u] = add2(acc1[u], t1[u]); }
        }

        // ---- store: smem (p<2) or global (p=2); lanes si<4 hold quad si --
        if (si < 4) {
            if (p < 2) {
                store_quad(O3 + p * O3P + nl * O3STR + 4 * si,
                           acc0[0], acc0[1], base0);
                store_quad(O3 + p * O3P + (nl + 16) * O3STR + 4 * si,
                           acc1[0], acc1[1], base1);
            } else {
                store_quad(hout + ((size_t)(nbase + nl) * 32 + f4) * 16 + 4 * si,
                           acc0[0], acc0[1], base0);
                store_quad(hout + ((size_t)(nbase + nl + 16) * 32 + f4) * 16 + 4 * si,
                           acc1[0], acc1[1], base1);
            }
        }
        __syncthreads();   // O3 visible; Ssm/Brows free for next phase
    }
}

// ---------------------------------------------------------------------------
// Root. Block per n (512 blocks, 32 threads), warp-shfl reduce.
// ---------------------------------------------------------------------------
__global__ void __launch_bounds__(32) root_kernel(
    const float* __restrict__ h4, const float* __restrict__ Wroot,
    float* __restrict__ out)
{
    const int n = blockIdx.x;
    const int t = threadIdx.x;
    const float4* hp = (const float4*)(h4 + (size_t)n * 512);

    float4 a = make_float4(0.f, 0.f, 0.f, 0.f);
    #pragma unroll
    for (int r = 0; r < 4; r++) {
        float4 q = hp[t + 32 * r];
        a.x += q.x; a.y += q.y; a.z += q.z; a.w += q.w;
    }
    #pragma unroll
    for (int st = 4; st <= 16; st <<= 1) {
        a.x += __shfl_xor_sync(0xffffffffu, a.x, st);
        a.y += __shfl_xor_sync(0xffffffffu, a.y, st);
        a.z += __shfl_xor_sync(0xffffffffu, a.z, st);
        a.w += __shfl_xor_sync(0xffffffffu, a.w, st);
    }
    __shared__ float sred[16];
    if (t < 4) { sred[4*t] = a.x; sred[4*t+1] = a.y; sred[4*t+2] = a.z; sred[4*t+3] = a.w; }
    __syncwarp();

    if (t == 0) {
        float w[16];
        #pragma unroll
        for (int k = 0; k < 16; k++) w[k] = Wroot[k];
        float wm = w[0];
        #pragma unroll
        for (int k = 1; k < 16; k++) wm = fmaxf(wm, w[k]);
        float Z = 0.f;
        #pragma unroll
        for (int k = 0; k < 16; k++) Z += __expf(w[k] - wm);
        const float lz = __logf(Z) + wm;

        float tv[16];
        float tm = -1e30f;
        #pragma unroll
        for (int k = 0; k < 16; k++) {
            tv[k] = sred[k] + w[k] - lz;
            tm = fmaxf(tm, tv[k]);
        }
        float ss = 0.f;
        #pragma unroll
        for (int k = 0; k < 16; k++) ss += __expf(tv[k] - tm);
        out[n] = __logf(ss) + tm;
    }
}

// ---------------------------------------------------------------------------
extern "C" void kernel_launch(void* const* d_in, const int* in_sizes, int n_in,
                              void* d_out, int out_size)
{
    const float* x  = (const float*)d_in[0];
    const float* W1 = (const float*)d_in[1];
    const float* W2 = (const float*)d_in[2];
    const float* W3 = (const float*)d_in[3];
    const float* W4 = (const float*)d_in[4];
    const float* Wr = (const float*)d_in[5];
    float* out = (float*)d_out;

    float *hA, *hB;
    cudaGetSymbolAddress((void**)&hA, g_hA);
    cudaGetSymbolAddress((void**)&hB, g_hB);

    const size_t sm1  = (4224 + 128 * 34) * 4;           // MS=1 : 34304
    const size_t sm2  = (4224 +  64 * 34) * 4;           // MS=2 : 25600
    const size_t sm34 = (4224 + 544 + 2 * 32 * 20) * 4;  // fused: 24192

    layer_kernel<1><<<dim3(256, 2), 128, sm1 >>>(x,  W1, hA, 512);  // L1
    layer_kernel<2><<<dim3(128, 4), 128, sm2 >>>(hA, W2, hB, 256);  // L2
    l34_kernel<<<dim3(32, 16), 128, sm34>>>(hB, W3, W4, hA);        // L3+L4

    root_kernel<<<512, 32>>>(hA, Wr, out);
}

// round 15
// speedup vs baseline: 1.1742x; 1.1499x over previous
#include <cuda_runtime.h>
#include <cstddef>

typedef unsigned long long u64;

// Scratch (static __device__ — no allocations allowed).
__device__ float g_hA[2097152];   // L1 out (512*256*16), reused by L3 out
__device__ float g_hB[1048576];   // L2 out (512*128*16), reused by L4 out

// ---------------- packed f32x2 helpers (dual-fp32 pipe) --------------------
__device__ __forceinline__ void fma2(u64& d, u64 a, u64 b) {
    asm("fma.rn.f32x2 %0, %1, %2, %0;" : "+l"(d) : "l"(a), "l"(b));
}
__device__ __forceinline__ u64 add2(u64 a, u64 b) {
    u64 d; asm("add.rn.f32x2 %0, %1, %2;" : "=l"(d) : "l"(a), "l"(b)); return d;
}
__device__ __forceinline__ u64 pack2(float x) {
    u64 d; asm("mov.b64 %0, {%1, %1};" : "=l"(d) : "f"(x)); return d;
}
__device__ __forceinline__ void unpack2(u64 a, float& lo, float& hi) {
    asm("mov.b64 {%0, %1}, %2;" : "=f"(lo), "=f"(hi) : "l"(a));
}

// store one k-quad: log + base, float4 store.
__device__ __forceinline__ void store_quad(float* dst, u64 lo, u64 hi, float base) {
    float x0, x1, x2, x3;
    unpack2(lo, x0, x1);
    unpack2(hi, x2, x3);
    *(float4*)dst = make_float4(__logf(x0) + base, __logf(x1) + base,
                                __logf(x2) + base, __logf(x3) + base);
}

// ---------------------------------------------------------------------------
// Layer kernel — R11 machinery (best passing: 82.5us). Fused normalized
// weight softmax; m-split over i (MS lanes, XOR-swizzled S, broadcast
// LDS.128); NT=2 samples/thread.
// NEW vs R11: MINB template param. L1 now runs MS=2 at grid(256,4)=1024
// blocks with MINB=7 (single wave, 43% occupancy) — L1 is the one
// issue-bound layer, so occupancy should finally pay there. L2/L3/L4
// instantiations keep MINB=2 (no reg cap, R11-equivalent codegen).
// ---------------------------------------------------------------------------
template<int MS, int MINB>
__global__ void __launch_bounds__(128, MINB) layer_kernel(
    const float* __restrict__ hin, const float* __restrict__ Wl,
    float* __restrict__ hout, int F_in)
{
    constexpr int G    = 16 / MS;
    constexpr int NSL  = 128 / MS;
    constexpr int LG   = (G == 16) ? 4 : (G == 8) ? 3 : (G == 4) ? 2 : 1;
    constexpr int XRM  = (MS < 4 ? MS : 4) - 1;
    constexpr int UJ   = (MS <= 2) ? 2 : 4;
    constexpr int REDA = 4096;
    constexpr int REDB = 4160;
    constexpr int BR   = 4224;

    extern __shared__ float sm[];
    float* Ssm   = sm;
    float* Brows = sm + BR;

    const int tid  = threadIdx.x;
    const int si   = tid & (MS - 1);
    const int nl   = tid / MS;
    const int f    = blockIdx.x;
    const int F_out = F_in >> 1;
    const int n0   = blockIdx.y * (2 * NSL) + nl;
    const int n1   = n0 + NSL;
    const int xr   = si & XRM;
    const int q    = tid & 3;
    const int wid  = tid >> 5;
    const int lane = tid & 31;

    // ---- Fused weight softmax (fully normalized) -----------------------
    float4 wreg[8];
    {
        const float4* Wg = (const float4*)(Wl + (size_t)f * 4096);
        #pragma unroll
        for (int s8 = 0; s8 < 8; s8++) wreg[s8] = Wg[tid + 128 * s8];
    }
    float4 mx4 = wreg[0];
    #pragma unroll
    for (int s8 = 1; s8 < 8; s8++) {
        mx4.x = fmaxf(mx4.x, wreg[s8].x); mx4.y = fmaxf(mx4.y, wreg[s8].y);
        mx4.z = fmaxf(mx4.z, wreg[s8].z); mx4.w = fmaxf(mx4.w, wreg[s8].w);
    }
    #pragma unroll
    for (int off = 4; off < 32; off <<= 1) {
        mx4.x = fmaxf(mx4.x, __shfl_xor_sync(0xffffffffu, mx4.x, off));
        mx4.y = fmaxf(mx4.y, __shfl_xor_sync(0xffffffffu, mx4.y, off));
        mx4.z = fmaxf(mx4.z, __shfl_xor_sync(0xffffffffu, mx4.z, off));
        mx4.w = fmaxf(mx4.w, __shfl_xor_sync(0xffffffffu, mx4.w, off));
    }
    if (lane < 4) *(float4*)(sm + REDA + wid * 16 + q * 4) = mx4;
    __syncthreads();
    {
        mx4 = *(const float4*)(sm + REDA + q * 4);
        #pragma unroll
        for (int w = 1; w < 4; w++) {
            float4 t = *(const float4*)(sm + REDA + w * 16 + q * 4);
            mx4.x = fmaxf(mx4.x, t.x); mx4.y = fmaxf(mx4.y, t.y);
            mx4.z = fmaxf(mx4.z, t.z); mx4.w = fmaxf(mx4.w, t.w);
        }
    }
    float4 sum4 = make_float4(0.f, 0.f, 0.f, 0.f);
    #pragma unroll
    for (int s8 = 0; s8 < 8; s8++) {
        wreg[s8].x = __expf(wreg[s8].x - mx4.x);
        wreg[s8].y = __expf(wreg[s8].y - mx4.y);
        wreg[s8].z = __expf(wreg[s8].z - mx4.z);
        wreg[s8].w = __expf(wreg[s8].w - mx4.w);
        sum4.x += wreg[s8].x; sum4.y += wreg[s8].y;
        sum4.z += wreg[s8].z; sum4.w += wreg[s8].w;
    }
    #pragma unroll
    for (int off = 4; off < 32; off <<= 1) {
        sum4.x += __shfl_xor_sync(0xffffffffu, sum4.x, off);
        sum4.y += __shfl_xor_sync(0xffffffffu, sum4.y, off);
        sum4.z += __shfl_xor_sync(0xffffffffu, sum4.z, off);
        sum4.w += __shfl_xor_sync(0xffffffffu, sum4.w, off);
    }
    if (lane < 4) *(float4*)(sm + REDB + wid * 16 + q * 4) = sum4;
    __syncthreads();
    {
        sum4 = *(const float4*)(sm + REDB + q * 4);
        #pragma unroll
        for (int w = 1; w < 4; w++) {
            float4 t = *(const float4*)(sm + REDB + w * 16 + q * 4);
            sum4.x += t.x; sum4.y += t.y; sum4.z += t.z; sum4.w += t.w;
        }
    }
    const float4 inv4 = make_float4(1.f / sum4.x, 1.f / sum4.y,
                                    1.f / sum4.z, 1.f / sum4.w);
    #pragma unroll
    for (int s8 = 0; s8 < 8; s8++) {
        const int idx = tid + 128 * s8;
        const int m = idx >> 2;
        float4 e = make_float4(wreg[s8].x * inv4.x, wreg[s8].y * inv4.y,
                               wreg[s8].z * inv4.z, wreg[s8].w * inv4.w);
        const int xi = (m >> (4 + LG)) & XRM;
        *(float4*)(Ssm + m * 16 + 4 * (q ^ xi)) = e;
    }

    // ---- Prologue -------------------------------------------------------
    float a0[G], a1[G];
    float base0, base1;
    float* row = Brows + nl * 34;
    {
        float av[G], bv[G];
        const float* h0 = hin + ((size_t)n0 * F_in + 2 * f) * 16 + G * si;
        if constexpr (G >= 4) {
            #pragma unroll
            for (int c = 0; c < G / 4; c++) {
                ((float4*)av)[c] = *(const float4*)(h0 + 4 * c);
                ((float4*)bv)[c] = *(const float4*)(h0 + 16 + 4 * c);
            }
        } else {
            ((float2*)av)[0] = *(const float2*)(h0);
            ((float2*)bv)[0] = *(const float2*)(h0 + 16);
        }
        float l = av[0], r = bv[0];
        #pragma unroll
        for (int d = 1; d < G; d++) { l = fmaxf(l, av[d]); r = fmaxf(r, bv[d]); }
        #pragma unroll
        for (int rr = 1; rr < MS; rr <<= 1) {
            l = fmaxf(l, __shfl_xor_sync(0xffffffffu, l, rr));
            r = fmaxf(r, __shfl_xor_sync(0xffffffffu, r, rr));
        }
        #pragma unroll
        for (int d = 0; d < G; d++) {
            a0[d] = __expf(av[d] - l);
            row[2 * (G * si + d)] = __expf(bv[d] - r);
        }
        base0 = l + r;
    }
    {
        float av[G], bv[G];
        const float* h1 = hin + ((size_t)n1 * F_in + 2 * f) * 16 + G * si;
        if constexpr (G >= 4) {
            #pragma unroll
            for (int c = 0; c < G / 4; c++) {
                ((float4*)av)[c] = *(const float4*)(h1 + 4 * c);
                ((float4*)bv)[c] = *(const float4*)(h1 + 16 + 4 * c);
            }
        } else {
            ((float2*)av)[0] = *(const float2*)(h1);
            ((float2*)bv)[0] = *(const float2*)(h1 + 16);
        }
        float l = av[0], r = bv[0];
        #pragma unroll
        for (int d = 1; d < G; d++) { l = fmaxf(l, av[d]); r = fmaxf(r, bv[d]); }
        #pragma unroll
        for (int rr = 1; rr < MS; rr <<= 1) {
            l = fmaxf(l, __shfl_xor_sync(0xffffffffu, l, rr));
            r = fmaxf(r, __shfl_xor_sync(0xffffffffu, r, rr));
        }
        #pragma unroll
        for (int d = 0; d < G; d++) {
            a1[d] = __expf(av[d] - l);
            row[2 * (G * si + d) + 1] = __expf(bv[d] - r);
        }
        base1 = l + r;
    }
    __syncthreads();

    // ---- Mainloop -------------------------------------------------------
    u64 acc0[8], acc1[8];
    #pragma unroll
    for (int u = 0; u < 8; u++) { acc0[u] = 0ull; acc1[u] = 0ull; }

    const float* pq0 = Ssm + si * (G * 256) + 4 * (0 ^ xr);
    const float* pq1 = Ssm + si * (G * 256) + 4 * (1 ^ xr);
    const float* pq2 = Ssm + si * (G * 256) + 4 * (2 ^ xr);
    const float* pq3 = Ssm + si * (G * 256) + 4 * (3 ^ xr);
    const u64* rowq = (const u64*)row;

    #pragma unroll UJ
    for (int j = 0; j < 16; j++) {
        float b0, b1;
        unpack2(rowq[j], b0, b1);
        const int jo = j * 16;
        #pragma unroll
        for (int d = 0; d < G; d++) {
            const int o = d * 256 + jo;
            const u64 p0 = pack2(a0[d] * b0);
            const u64 p1 = pack2(a1[d] * b1);
            ulonglong2 w;
            w = *(const ulonglong2*)(pq0 + o);
            fma2(acc0[0], p0, w.x); fma2(acc0[1], p0, w.y);
            fma2(acc1[0], p1, w.x); fma2(acc1[1], p1, w.y);
            w = *(const ulonglong2*)(pq1 + o);
            fma2(acc0[2], p0, w.x); fma2(acc0[3], p0, w.y);
            fma2(acc1[2], p1, w.x); fma2(acc1[3], p1, w.y);
            w = *(const ulonglong2*)(pq2 + o);
            fma2(acc0[4], p0, w.x); fma2(acc0[5], p0, w.y);
            fma2(acc1[4], p1, w.x); fma2(acc1[5], p1, w.y);
            w = *(const ulonglong2*)(pq3 + o);
            fma2(acc0[6], p0, w.x); fma2(acc0[7], p0, w.y);
            fma2(acc1[6], p1, w.x); fma2(acc1[7], p1, w.y);
        }
    }

    // ---- Reduce across si lanes -----------------------------------------
    if constexpr (MS >= 2) {
        u64 t0[8], t1[8];
        #pragma unroll
        for (int u = 0; u < 8; u++) {
            t0[u] = __shfl_xor_sync(0xffffffffu, acc0[u ^ 2], 1);
            t1[u] = __shfl_xor_sync(0xffffffffu, acc1[u ^ 2], 1);
        }
        #pragma unroll
        for (int u = 0; u < 8; u++) { acc0[u] = add2(acc0[u], t0[u]); acc1[u] = add2(acc1[u], t1[u]); }
    }
    if constexpr (MS >= 4) {
        u64 t0[8], t1[8];
        #pragma unroll
        for (int u = 0; u < 8; u++) {
            t0[u] = __shfl_xor_sync(0xffffffffu, acc0[u ^ 4], 2);
            t1[u] = __shfl_xor_sync(0xffffffffu, acc1[u ^ 4], 2);
        }
        #pragma unroll
        for (int u = 0; u < 8; u++) { acc0[u] = add2(acc0[u], t0[u]); acc1[u] = add2(acc1[u], t1[u]); }
    }
    if constexpr (MS == 8) {
        u64 t0[8], t1[8];
        #pragma unroll
        for (int u = 0; u < 8; u++) {
            t0[u] = __shfl_xor_sync(0xffffffffu, acc0[u], 4);
            t1[u] = __shfl_xor_sync(0xffffffffu, acc1[u], 4);
        }
        #pragma unroll
        for (int u = 0; u < 8; u++) { acc0[u] = add2(acc0[u], t0[u]); acc1[u] = add2(acc1[u], t1[u]); }
    }

    // ---- Store -----------------------------------------------------------
    float* o0p = hout + ((size_t)n0 * F_out + f) * 16;
    float* o1p = hout + ((size_t)n1 * F_out + f) * 16;
    if constexpr (MS == 1) {
        #pragma unroll
        for (int qq = 0; qq < 4; qq++) {
            store_quad(o0p + 4 * qq, acc0[2 * qq], acc0[2 * qq + 1], base0);
            store_quad(o1p + 4 * qq, acc1[2 * qq], acc1[2 * qq + 1], base1);
        }
    } else if constexpr (MS == 2) {
        const int ka = si ? 12 : 0, kb = si ? 8 : 4;
        u64 A0 = si ? acc0[4] : acc0[0], A1 = si ? acc0[5] : acc0[1];
        u64 B0 = si ? acc0[6] : acc0[2], B1 = si ? acc0[7] : acc0[3];
        store_quad(o0p + ka, A0, A1, base0);
        store_quad(o0p + kb, B0, B1, base0);
        u64 C0 = si ? acc1[4] : acc1[0], C1 = si ? acc1[5] : acc1[1];
        u64 D0 = si ? acc1[6] : acc1[2], D1 = si ? acc1[7] : acc1[3];
        store_quad(o1p + ka, C0, C1, base1);
        store_quad(o1p + kb, D0, D1, base1);
    } else if constexpr (MS == 4) {
        store_quad(o0p + 4 * si, acc0[0], acc0[1], base0);
        store_quad(o1p + 4 * si, acc1[0], acc1[1], base1);
    } else { // MS == 8
        if (si < 4) {
            store_quad(o0p + 4 * si, acc0[0], acc0[1], base0);
            store_quad(o1p + 4 * si, acc1[0], acc1[1], base1);
        }
    }
}

// ---------------------------------------------------------------------------
// Root. Block per n (512 blocks, 32 threads), warp-shfl reduce.
// ---------------------------------------------------------------------------
__global__ void __launch_bounds__(32) root_kernel(
    const float* __restrict__ h4, const float* __restrict__ Wroot,
    float* __restrict__ out)
{
    const int n = blockIdx.x;
    const int t = threadIdx.x;
    const float4* hp = (const float4*)(h4 + (size_t)n * 512);

    float4 a = make_float4(0.f, 0.f, 0.f, 0.f);
    #pragma unroll
    for (int r = 0; r < 4; r++) {
        float4 q = hp[t + 32 * r];
        a.x += q.x; a.y += q.y; a.z += q.z; a.w += q.w;
    }
    #pragma unroll
    for (int st = 4; st <= 16; st <<= 1) {
        a.x += __shfl_xor_sync(0xffffffffu, a.x, st);
        a.y += __shfl_xor_sync(0xffffffffu, a.y, st);
        a.z += __shfl_xor_sync(0xffffffffu, a.z, st);
        a.w += __shfl_xor_sync(0xffffffffu, a.w, st);
    }
    __shared__ float sred[16];
    if (t < 4) { sred[4*t] = a.x; sred[4*t+1] = a.y; sred[4*t+2] = a.z; sred[4*t+3] = a.w; }
    __syncwarp();

    if (t == 0) {
        float w[16];
        #pragma unroll
        for (int k = 0; k < 16; k++) w[k] = Wroot[k];
        float wm = w[0];
        #pragma unroll
        for (int k = 1; k < 16; k++) wm = fmaxf(wm, w[k]);
        float Z = 0.f;
        #pragma unroll
        for (int k = 0; k < 16; k++) Z += __expf(w[k] - wm);
        const float lz = __logf(Z) + wm;

        float tv[16];
        float tm = -1e30f;
        #pragma unroll
        for (int k = 0; k < 16; k++) {
            tv[k] = sred[k] + w[k] - lz;
            tm = fmaxf(tm, tv[k]);
        }
        float ss = 0.f;
        #pragma unroll
        for (int k = 0; k < 16; k++) ss += __expf(tv[k] - tm);
        out[n] = __logf(ss) + tm;
    }
}

// ---------------------------------------------------------------------------
extern "C" void kernel_launch(void* const* d_in, const int* in_sizes, int n_in,
                              void* d_out, int out_size)
{
    const float* x  = (const float*)d_in[0];
    const float* W1 = (const float*)d_in[1];
    const float* W2 = (const float*)d_in[2];
    const float* W3 = (const float*)d_in[3];
    const float* W4 = (const float*)d_in[4];
    const float* Wr = (const float*)d_in[5];
    float* out = (float*)d_out;

    float *hA, *hB;
    cudaGetSymbolAddress((void**)&hA, g_hA);
    cudaGetSymbolAddress((void**)&hB, g_hB);

    // smem = (4224 + NSL*34) floats; all < 48KB.
    const size_t sm2 = (4224 +  64 * 34) * 4;  // MS=2 : 25600
    const size_t sm4 = (4224 +  32 * 34) * 4;  // MS=4 : 21248
    const size_t sm8 = (4224 +  16 * 34) * 4;  // MS=8 : 19072

    // L1: MS=2 at 1024 blocks, MINB=7 -> single wave at 43% occupancy
    // (L1 is the issue-bound layer; occupancy should pay here).
    // L2/L3/L4: verbatim R11 shapes (512 blocks, MINB=2 = no reg cap).
    layer_kernel<2, 7><<<dim3(256, 4), 128, sm2>>>(x,  W1, hA, 512);
    layer_kernel<2, 2><<<dim3(128, 4), 128, sm2>>>(hA, W2, hB, 256);
    layer_kernel<4, 2><<<dim3(64, 8),  128, sm4>>>(hB, W3, hA, 128);
    layer_kernel<8, 2><<<dim3(32, 16), 128, sm8>>>(hA, W4, hB, 64);

    root_kernel<<<512, 32>>>(hB, Wr, out);
}

// round 16
// speedup vs baseline: 1.1761x; 1.0016x over previous
#include <cuda_runtime.h>
#include <cstddef>

typedef unsigned long long u64;

// Scratch (static __device__ — no allocations allowed).
__device__ float g_hA[2097152];   // L1 out (512*256*16), reused by L3 out
__device__ float g_hB[1048576];   // L2 out (512*128*16), reused by L4 out

// ---------------- packed f32x2 helpers (dual-fp32 pipe) --------------------
__device__ __forceinline__ void fma2(u64& d, u64 a, u64 b) {
    asm("fma.rn.f32x2 %0, %1, %2, %0;" : "+l"(d) : "l"(a), "l"(b));
}
__device__ __forceinline__ u64 add2(u64 a, u64 b) {
    u64 d; asm("add.rn.f32x2 %0, %1, %2;" : "=l"(d) : "l"(a), "l"(b)); return d;
}
__device__ __forceinline__ u64 pack2(float x) {
    u64 d; asm("mov.b64 %0, {%1, %1};" : "=l"(d) : "f"(x)); return d;
}
__device__ __forceinline__ void unpack2(u64 a, float& lo, float& hi) {
    asm("mov.b64 {%0, %1}, %2;" : "=f"(lo), "=f"(hi) : "l"(a));
}

// store one k-quad: log + base, float4 store.
__device__ __forceinline__ void store_quad(float* dst, u64 lo, u64 hi, float base) {
    float x0, x1, x2, x3;
    unpack2(lo, x0, x1);
    unpack2(hi, x2, x3);
    *(float4*)dst = make_float4(__logf(x0) + base, __logf(x1) + base,
                                __logf(x2) + base, __logf(x3) + base);
}

// ---------------------------------------------------------------------------
// Layer kernel — R15 verbatim (best passing: 80.3us). Fused normalized
// weight softmax; m-split over i (MS lanes, XOR-swizzled S, broadcast
// LDS.128); NT=2 samples/thread.
// L1: MS=2, grid(256,4)=1024 blocks, MINB=7 (single wave, 43% occ).
// L2/L3/L4: 512-block R11 shapes, MINB=2 (no reg cap).
// ---------------------------------------------------------------------------
template<int MS, int MINB>
__global__ void __launch_bounds__(128, MINB) layer_kernel(
    const float* __restrict__ hin, const float* __restrict__ Wl,
    float* __restrict__ hout, int F_in)
{
    constexpr int G    = 16 / MS;
    constexpr int NSL  = 128 / MS;
    constexpr int LG   = (G == 16) ? 4 : (G == 8) ? 3 : (G == 4) ? 2 : 1;
    constexpr int XRM  = (MS < 4 ? MS : 4) - 1;
    constexpr int UJ   = (MS <= 2) ? 2 : 4;
    constexpr int REDA = 4096;
    constexpr int REDB = 4160;
    constexpr int BR   = 4224;

    extern __shared__ float sm[];
    float* Ssm   = sm;
    float* Brows = sm + BR;

    const int tid  = threadIdx.x;
    const int si   = tid & (MS - 1);
    const int nl   = tid / MS;
    const int f    = blockIdx.x;
    const int F_out = F_in >> 1;
    const int n0   = blockIdx.y * (2 * NSL) + nl;
    const int n1   = n0 + NSL;
    const int xr   = si & XRM;
    const int q    = tid & 3;
    const int wid  = tid >> 5;
    const int lane = tid & 31;

    // ---- Fused weight softmax (fully normalized) -----------------------
    float4 wreg[8];
    {
        const float4* Wg = (const float4*)(Wl + (size_t)f * 4096);
        #pragma unroll
        for (int s8 = 0; s8 < 8; s8++) wreg[s8] = Wg[tid + 128 * s8];
    }
    float4 mx4 = wreg[0];
    #pragma unroll
    for (int s8 = 1; s8 < 8; s8++) {
        mx4.x = fmaxf(mx4.x, wreg[s8].x); mx4.y = fmaxf(mx4.y, wreg[s8].y);
        mx4.z = fmaxf(mx4.z, wreg[s8].z); mx4.w = fmaxf(mx4.w, wreg[s8].w);
    }
    #pragma unroll
    for (int off = 4; off < 32; off <<= 1) {
        mx4.x = fmaxf(mx4.x, __shfl_xor_sync(0xffffffffu, mx4.x, off));
        mx4.y = fmaxf(mx4.y, __shfl_xor_sync(0xffffffffu, mx4.y, off));
        mx4.z = fmaxf(mx4.z, __shfl_xor_sync(0xffffffffu, mx4.z, off));
        mx4.w = fmaxf(mx4.w, __shfl_xor_sync(0xffffffffu, mx4.w, off));
    }
    if (lane < 4) *(float4*)(sm + REDA + wid * 16 + q * 4) = mx4;
    __syncthreads();
    {
        mx4 = *(const float4*)(sm + REDA + q * 4);
        #pragma unroll
        for (int w = 1; w < 4; w++) {
            float4 t = *(const float4*)(sm + REDA + w * 16 + q * 4);
            mx4.x = fmaxf(mx4.x, t.x); mx4.y = fmaxf(mx4.y, t.y);
            mx4.z = fmaxf(mx4.z, t.z); mx4.w = fmaxf(mx4.w, t.w);
        }
    }
    float4 sum4 = make_float4(0.f, 0.f, 0.f, 0.f);
    #pragma unroll
    for (int s8 = 0; s8 < 8; s8++) {
        wreg[s8].x = __expf(wreg[s8].x - mx4.x);
        wreg[s8].y = __expf(wreg[s8].y - mx4.y);
        wreg[s8].z = __expf(wreg[s8].z - mx4.z);
        wreg[s8].w = __expf(wreg[s8].w - mx4.w);
        sum4.x += wreg[s8].x; sum4.y += wreg[s8].y;
        sum4.z += wreg[s8].z; sum4.w += wreg[s8].w;
    }
    #pragma unroll
    for (int off = 4; off < 32; off <<= 1) {
        sum4.x += __shfl_xor_sync(0xffffffffu, sum4.x, off);
        sum4.y += __shfl_xor_sync(0xffffffffu, sum4.y, off);
        sum4.z += __shfl_xor_sync(0xffffffffu, sum4.z, off);
        sum4.w += __shfl_xor_sync(0xffffffffu, sum4.w, off);
    }
    if (lane < 4) *(float4*)(sm + REDB + wid * 16 + q * 4) = sum4;
    __syncthreads();
    {
        sum4 = *(const float4*)(sm + REDB + q * 4);
        #pragma unroll
        for (int w = 1; w < 4; w++) {
            float4 t = *(const float4*)(sm + REDB + w * 16 + q * 4);
            sum4.x += t.x; sum4.y += t.y; sum4.z += t.z; sum4.w += t.w;
        }
    }
    const float4 inv4 = make_float4(1.f / sum4.x, 1.f / sum4.y,
                                    1.f / sum4.z, 1.f / sum4.w);
    #pragma unroll
    for (int s8 = 0; s8 < 8; s8++) {
        const int idx = tid + 128 * s8;
        const int m = idx >> 2;
        float4 e = make_float4(wreg[s8].x * inv4.x, wreg[s8].y * inv4.y,
                               wreg[s8].z * inv4.z, wreg[s8].w * inv4.w);
        const int xi = (m >> (4 + LG)) & XRM;
        *(float4*)(Ssm + m * 16 + 4 * (q ^ xi)) = e;
    }

    // ---- Prologue -------------------------------------------------------
    float a0[G], a1[G];
    float base0, base1;
    float* row = Brows + nl * 34;
    {
        float av[G], bv[G];
        const float* h0 = hin + ((size_t)n0 * F_in + 2 * f) * 16 + G * si;
        if constexpr (G >= 4) {
            #pragma unroll
            for (int c = 0; c < G / 4; c++) {
                ((float4*)av)[c] = *(const float4*)(h0 + 4 * c);
                ((float4*)bv)[c] = *(const float4*)(h0 + 16 + 4 * c);
            }
        } else {
            ((float2*)av)[0] = *(const float2*)(h0);
            ((float2*)bv)[0] = *(const float2*)(h0 + 16);
        }
        float l = av[0], r = bv[0];
        #pragma unroll
        for (int d = 1; d < G; d++) { l = fmaxf(l, av[d]); r = fmaxf(r, bv[d]); }
        #pragma unroll
        for (int rr = 1; rr < MS; rr <<= 1) {
            l = fmaxf(l, __shfl_xor_sync(0xffffffffu, l, rr));
            r = fmaxf(r, __shfl_xor_sync(0xffffffffu, r, rr));
        }
        #pragma unroll
        for (int d = 0; d < G; d++) {
            a0[d] = __expf(av[d] - l);
            row[2 * (G * si + d)] = __expf(bv[d] - r);
        }
        base0 = l + r;
    }
    {
        float av[G], bv[G];
        const float* h1 = hin + ((size_t)n1 * F_in + 2 * f) * 16 + G * si;
        if constexpr (G >= 4) {
            #pragma unroll
            for (int c = 0; c < G / 4; c++) {
                ((float4*)av)[c] = *(const float4*)(h1 + 4 * c);
                ((float4*)bv)[c] = *(const float4*)(h1 + 16 + 4 * c);
            }
        } else {
            ((float2*)av)[0] = *(const float2*)(h1);
            ((float2*)bv)[0] = *(const float2*)(h1 + 16);
        }
        float l = av[0], r = bv[0];
        #pragma unroll
        for (int d = 1; d < G; d++) { l = fmaxf(l, av[d]); r = fmaxf(r, bv[d]); }
        #pragma unroll
        for (int rr = 1; rr < MS; rr <<= 1) {
            l = fmaxf(l, __shfl_xor_sync(0xffffffffu, l, rr));
            r = fmaxf(r, __shfl_xor_sync(0xffffffffu, r, rr));
        }
        #pragma unroll
        for (int d = 0; d < G; d++) {
            a1[d] = __expf(av[d] - l);
            row[2 * (G * si + d) + 1] = __expf(bv[d] - r);
        }
        base1 = l + r;
    }
    __syncthreads();

    // ---- Mainloop -------------------------------------------------------
    u64 acc0[8], acc1[8];
    #pragma unroll
    for (int u = 0; u < 8; u++) { acc0[u] = 0ull; acc1[u] = 0ull; }

    const float* pq0 = Ssm + si * (G * 256) + 4 * (0 ^ xr);
    const float* pq1 = Ssm + si * (G * 256) + 4 * (1 ^ xr);
    const float* pq2 = Ssm + si * (G * 256) + 4 * (2 ^ xr);
    const float* pq3 = Ssm + si * (G * 256) + 4 * (3 ^ xr);
    const u64* rowq = (const u64*)row;

    #pragma unroll UJ
    for (int j = 0; j < 16; j++) {
        float b0, b1;
        unpack2(rowq[j], b0, b1);
        const int jo = j * 16;
        #pragma unroll
        for (int d = 0; d < G; d++) {
            const int o = d * 256 + jo;
            const u64 p0 = pack2(a0[d] * b0);
            const u64 p1 = pack2(a1[d] * b1);
            ulonglong2 w;
            w = *(const ulonglong2*)(pq0 + o);
            fma2(acc0[0], p0, w.x); fma2(acc0[1], p0, w.y);
            fma2(acc1[0], p1, w.x); fma2(acc1[1], p1, w.y);
            w = *(const ulonglong2*)(pq1 + o);
            fma2(acc0[2], p0, w.x); fma2(acc0[3], p0, w.y);
            fma2(acc1[2], p1, w.x); fma2(acc1[3], p1, w.y);
            w = *(const ulonglong2*)(pq2 + o);
            fma2(acc0[4], p0, w.x); fma2(acc0[5], p0, w.y);
            fma2(acc1[4], p1, w.x); fma2(acc1[5], p1, w.y);
            w = *(const ulonglong2*)(pq3 + o);
            fma2(acc0[6], p0, w.x); fma2(acc0[7], p0, w.y);
            fma2(acc1[6], p1, w.x); fma2(acc1[7], p1, w.y);
        }
    }

    // ---- Reduce across si lanes -----------------------------------------
    if constexpr (MS >= 2) {
        u64 t0[8], t1[8];
        #pragma unroll
        for (int u = 0; u < 8; u++) {
            t0[u] = __shfl_xor_sync(0xffffffffu, acc0[u ^ 2], 1);
            t1[u] = __shfl_xor_sync(0xffffffffu, acc1[u ^ 2], 1);
        }
        #pragma unroll
        for (int u = 0; u < 8; u++) { acc0[u] = add2(acc0[u], t0[u]); acc1[u] = add2(acc1[u], t1[u]); }
    }
    if constexpr (MS >= 4) {
        u64 t0[8], t1[8];
        #pragma unroll
        for (int u = 0; u < 8; u++) {
            t0[u] = __shfl_xor_sync(0xffffffffu, acc0[u ^ 4], 2);
            t1[u] = __shfl_xor_sync(0xffffffffu, acc1[u ^ 4], 2);
        }
        #pragma unroll
        for (int u = 0; u < 8; u++) { acc0[u] = add2(acc0[u], t0[u]); acc1[u] = add2(acc1[u], t1[u]); }
    }
    if constexpr (MS == 8) {
        u64 t0[8], t1[8];
        #pragma unroll
        for (int u = 0; u < 8; u++) {
            t0[u] = __shfl_xor_sync(0xffffffffu, acc0[u], 4);
            t1[u] = __shfl_xor_sync(0xffffffffu, acc1[u], 4);
        }
        #pragma unroll
        for (int u = 0; u < 8; u++) { acc0[u] = add2(acc0[u], t0[u]); acc1[u] = add2(acc1[u], t1[u]); }
    }

    // ---- Store -----------------------------------------------------------
    float* o0p = hout + ((size_t)n0 * F_out + f) * 16;
    float* o1p = hout + ((size_t)n1 * F_out + f) * 16;
    if constexpr (MS == 1) {
        #pragma unroll
        for (int qq = 0; qq < 4; qq++) {
            store_quad(o0p + 4 * qq, acc0[2 * qq], acc0[2 * qq + 1], base0);
            store_quad(o1p + 4 * qq, acc1[2 * qq], acc1[2 * qq + 1], base1);
        }
    } else if constexpr (MS == 2) {
        const int ka = si ? 12 : 0, kb = si ? 8 : 4;
        u64 A0 = si ? acc0[4] : acc0[0], A1 = si ? acc0[5] : acc0[1];
        u64 B0 = si ? acc0[6] : acc0[2], B1 = si ? acc0[7] : acc0[3];
        store_quad(o0p + ka, A0, A1, base0);
        store_quad(o0p + kb, B0, B1, base0);
        u64 C0 = si ? acc1[4] : acc1[0], C1 = si ? acc1[5] : acc1[1];
        u64 D0 = si ? acc1[6] : acc1[2], D1 = si ? acc1[7] : acc1[3];
        store_quad(o1p + ka, C0, C1, base1);
        store_quad(o1p + kb, D0, D1, base1);
    } else if constexpr (MS == 4) {
        store_quad(o0p + 4 * si, acc0[0], acc0[1], base0);
        store_quad(o1p + 4 * si, acc1[0], acc1[1], base1);
    } else { // MS == 8
        if (si < 4) {
            store_quad(o0p + 4 * si, acc0[0], acc0[1], base0);
            store_quad(o1p + 4 * si, acc1[0], acc1[1], base1);
        }
    }
}

// ---------------------------------------------------------------------------
// Root — WIDENED: 128 blocks x 128 threads; each of the 4 warps owns one n
// (n = 4*bx + wid). Per-warp smem reduction buffers. 4x fewer blocks, 4
// warps co-resident per block slot -> latency hidden vs R15's 1-warp blocks.
// ---------------------------------------------------------------------------
__global__ void __launch_bounds__(128) root_kernel(
    const float* __restrict__ h4, const float* __restrict__ Wroot,
    float* __restrict__ out)
{
    const int tid  = threadIdx.x;
    const int wid  = tid >> 5;
    const int t    = tid & 31;
    const int n    = blockIdx.x * 4 + wid;
    const float4* hp = (const float4*)(h4 + (size_t)n * 512);

    float4 a = make_float4(0.f, 0.f, 0.f, 0.f);
    #pragma unroll
    for (int r = 0; r < 4; r++) {
        float4 q = hp[t + 32 * r];
        a.x += q.x; a.y += q.y; a.z += q.z; a.w += q.w;
    }
    #pragma unroll
    for (int st = 4; st <= 16; st <<= 1) {
        a.x += __shfl_xor_sync(0xffffffffu, a.x, st);
        a.y += __shfl_xor_sync(0xffffffffu, a.y, st);
        a.z += __shfl_xor_sync(0xffffffffu, a.z, st);
        a.w += __shfl_xor_sync(0xffffffffu, a.w, st);
    }
    __shared__ float sred[4][16];
    if (t < 4) {
        sred[wid][4*t]   = a.x; sred[wid][4*t+1] = a.y;
        sred[wid][4*t+2] = a.z; sred[wid][4*t+3] = a.w;
    }
    __syncwarp();

    if (t == 0) {
        float w[16];
        #pragma unroll
        for (int k = 0; k < 16; k++) w[k] = Wroot[k];
        float wm = w[0];
        #pragma unroll
        for (int k = 1; k < 16; k++) wm = fmaxf(wm, w[k]);
        float Z = 0.f;
        #pragma unroll
        for (int k = 0; k < 16; k++) Z += __expf(w[k] - wm);
        const float lz = __logf(Z) + wm;

        float tv[16];
        float tm = -1e30f;
        #pragma unroll
        for (int k = 0; k < 16; k++) {
            tv[k] = sred[wid][k] + w[k] - lz;
            tm = fmaxf(tm, tv[k]);
        }
        float ss = 0.f;
        #pragma unroll
        for (int k = 0; k < 16; k++) ss += __expf(tv[k] - tm);
        out[n] = __logf(ss) + tm;
    }
}

// ---------------------------------------------------------------------------
extern "C" void kernel_launch(void* const* d_in, const int* in_sizes, int n_in,
                              void* d_out, int out_size)
{
    const float* x  = (const float*)d_in[0];
    const float* W1 = (const float*)d_in[1];
    const float* W2 = (const float*)d_in[2];
    const float* W3 = (const float*)d_in[3];
    const float* W4 = (const float*)d_in[4];
    const float* Wr = (const float*)d_in[5];
    float* out = (float*)d_out;

    float *hA, *hB;
    cudaGetSymbolAddress((void**)&hA, g_hA);
    cudaGetSymbolAddress((void**)&hB, g_hB);

    // smem = (4224 + NSL*34) floats; all < 48KB.
    const size_t sm2 = (4224 +  64 * 34) * 4;  // MS=2 : 25600
    const size_t sm4 = (4224 +  32 * 34) * 4;  // MS=4 : 21248
    const size_t sm8 = (4224 +  16 * 34) * 4;  // MS=8 : 19072

    // R15 layer shapes (best): L1 promoted MS=2@1024 blocks single wave;
    // L2/L3/L4 at 512-block R11 shapes.
    layer_kernel<2, 7><<<dim3(256, 4), 128, sm2>>>(x,  W1, hA, 512);
    layer_kernel<2, 2><<<dim3(128, 4), 128, sm2>>>(hA, W2, hB, 256);
    layer_kernel<4, 2><<<dim3(64, 8),  128, sm4>>>(hB, W3, hA, 128);
    layer_kernel<8, 2><<<dim3(32, 16), 128, sm8>>>(hA, W4, hB, 64);

    root_kernel<<<128, 128>>>(hB, Wr, out);
}

// round 17
// speedup vs baseline: 1.1771x; 1.0008x over previous
#include <cuda_runtime.h>
#include <cstddef>

typedef unsigned long long u64;

// Scratch (static __device__ — no allocations allowed).
__device__ float g_hA[2097152];   // L1 out (512*256*16), reused by L3 out
__device__ float g_hB[1048576];   // L2 out (512*128*16), reused by L4 out

// ---------------- packed f32x2 helpers (dual-fp32 pipe) --------------------
__device__ __forceinline__ void fma2(u64& d, u64 a, u64 b) {
    asm("fma.rn.f32x2 %0, %1, %2, %0;" : "+l"(d) : "l"(a), "l"(b));
}
__device__ __forceinline__ u64 add2(u64 a, u64 b) {
    u64 d; asm("add.rn.f32x2 %0, %1, %2;" : "=l"(d) : "l"(a), "l"(b)); return d;
}
__device__ __forceinline__ u64 pack2(float x) {
    u64 d; asm("mov.b64 %0, {%1, %1};" : "=l"(d) : "f"(x)); return d;
}
__device__ __forceinline__ void unpack2(u64 a, float& lo, float& hi) {
    asm("mov.b64 {%0, %1}, %2;" : "=f"(lo), "=f"(hi) : "l"(a));
}

// store one k-quad: log + base, float4 store.
__device__ __forceinline__ void store_quad(float* dst, u64 lo, u64 hi, float base) {
    float x0, x1, x2, x3;
    unpack2(lo, x0, x1);
    unpack2(hi, x2, x3);
    *(float4*)dst = make_float4(__logf(x0) + base, __logf(x1) + base,
                                __logf(x2) + base, __logf(x3) + base);
}

// ---------------------------------------------------------------------------
// Layer body — R11 machinery verbatim. Fused normalized weight softmax;
// m-split over i (MS lanes, XOR-swizzled S, broadcast LDS.128); NT=2.
// Shared by both __global__ wrappers below so L1 can carry a reg cap while
// L2/L3/L4 keep R11's exact default-launch_bounds codegen (76 regs @ MS=8).
// ---------------------------------------------------------------------------
template<int MS>
__device__ __forceinline__ void layer_body(
    const float* __restrict__ hin, const float* __restrict__ Wl,
    float* __restrict__ hout, int F_in)
{
    constexpr int G    = 16 / MS;
    constexpr int NSL  = 128 / MS;
    constexpr int LG   = (G == 16) ? 4 : (G == 8) ? 3 : (G == 4) ? 2 : 1;
    constexpr int XRM  = (MS < 4 ? MS : 4) - 1;
    constexpr int UJ   = (MS <= 2) ? 2 : 4;
    constexpr int REDA = 4096;
    constexpr int REDB = 4160;
    constexpr int BR   = 4224;

    extern __shared__ float sm[];
    float* Ssm   = sm;
    float* Brows = sm + BR;

    const int tid  = threadIdx.x;
    const int si   = tid & (MS - 1);
    const int nl   = tid / MS;
    const int f    = blockIdx.x;
    const int F_out = F_in >> 1;
    const int n0   = blockIdx.y * (2 * NSL) + nl;
    const int n1   = n0 + NSL;
    const int xr   = si & XRM;
    const int q    = tid & 3;
    const int wid  = tid >> 5;
    const int lane = tid & 31;

    // ---- Fused weight softmax (fully normalized) -----------------------
    float4 wreg[8];
    {
        const float4* Wg = (const float4*)(Wl + (size_t)f * 4096);
        #pragma unroll
        for (int s8 = 0; s8 < 8; s8++) wreg[s8] = Wg[tid + 128 * s8];
    }
    float4 mx4 = wreg[0];
    #pragma unroll
    for (int s8 = 1; s8 < 8; s8++) {
        mx4.x = fmaxf(mx4.x, wreg[s8].x); mx4.y = fmaxf(mx4.y, wreg[s8].y);
        mx4.z = fmaxf(mx4.z, wreg[s8].z); mx4.w = fmaxf(mx4.w, wreg[s8].w);
    }
    #pragma unroll
    for (int off = 4; off < 32; off <<= 1) {
        mx4.x = fmaxf(mx4.x, __shfl_xor_sync(0xffffffffu, mx4.x, off));
        mx4.y = fmaxf(mx4.y, __shfl_xor_sync(0xffffffffu, mx4.y, off));
        mx4.z = fmaxf(mx4.z, __shfl_xor_sync(0xffffffffu, mx4.z, off));
        mx4.w = fmaxf(mx4.w, __shfl_xor_sync(0xffffffffu, mx4.w, off));
    }
    if (lane < 4) *(float4*)(sm + REDA + wid * 16 + q * 4) = mx4;
    __syncthreads();
    {
        mx4 = *(const float4*)(sm + REDA + q * 4);
        #pragma unroll
        for (int w = 1; w < 4; w++) {
            float4 t = *(const float4*)(sm + REDA + w * 16 + q * 4);
            mx4.x = fmaxf(mx4.x, t.x); mx4.y = fmaxf(mx4.y, t.y);
            mx4.z = fmaxf(mx4.z, t.z); mx4.w = fmaxf(mx4.w, t.w);
        }
    }
    float4 sum4 = make_float4(0.f, 0.f, 0.f, 0.f);
    #pragma unroll
    for (int s8 = 0; s8 < 8; s8++) {
        wreg[s8].x = __expf(wreg[s8].x - mx4.x);
        wreg[s8].y = __expf(wreg[s8].y - mx4.y);
        wreg[s8].z = __expf(wreg[s8].z - mx4.z);
        wreg[s8].w = __expf(wreg[s8].w - mx4.w);
        sum4.x += wreg[s8].x; sum4.y += wreg[s8].y;
        sum4.z += wreg[s8].z; sum4.w += wreg[s8].w;
    }
    #pragma unroll
    for (int off = 4; off < 32; off <<= 1) {
        sum4.x += __shfl_xor_sync(0xffffffffu, sum4.x, off);
        sum4.y += __shfl_xor_sync(0xffffffffu, sum4.y, off);
        sum4.z += __shfl_xor_sync(0xffffffffu, sum4.z, off);
        sum4.w += __shfl_xor_sync(0xffffffffu, sum4.w, off);
    }
    if (lane < 4) *(float4*)(sm + REDB + wid * 16 + q * 4) = sum4;
    __syncthreads();
    {
        sum4 = *(const float4*)(sm + REDB + q * 4);
        #pragma unroll
        for (int w = 1; w < 4; w++) {
            float4 t = *(const float4*)(sm + REDB + w * 16 + q * 4);
            sum4.x += t.x; sum4.y += t.y; sum4.z += t.z; sum4.w += t.w;
        }
    }
    const float4 inv4 = make_float4(1.f / sum4.x, 1.f / sum4.y,
                                    1.f / sum4.z, 1.f / sum4.w);
    #pragma unroll
    for (int s8 = 0; s8 < 8; s8++) {
        const int idx = tid + 128 * s8;
        const int m = idx >> 2;
        float4 e = make_float4(wreg[s8].x * inv4.x, wreg[s8].y * inv4.y,
                               wreg[s8].z * inv4.z, wreg[s8].w * inv4.w);
        const int xi = (m >> (4 + LG)) & XRM;
        *(float4*)(Ssm + m * 16 + 4 * (q ^ xi)) = e;
    }

    // ---- Prologue -------------------------------------------------------
    float a0[G], a1[G];
    float base0, base1;
    float* row = Brows + nl * 34;
    {
        float av[G], bv[G];
        const float* h0 = hin + ((size_t)n0 * F_in + 2 * f) * 16 + G * si;
        if constexpr (G >= 4) {
            #pragma unroll
            for (int c = 0; c < G / 4; c++) {
                ((float4*)av)[c] = *(const float4*)(h0 + 4 * c);
                ((float4*)bv)[c] = *(const float4*)(h0 + 16 + 4 * c);
            }
        } else {
            ((float2*)av)[0] = *(const float2*)(h0);
            ((float2*)bv)[0] = *(const float2*)(h0 + 16);
        }
        float l = av[0], r = bv[0];
        #pragma unroll
        for (int d = 1; d < G; d++) { l = fmaxf(l, av[d]); r = fmaxf(r, bv[d]); }
        #pragma unroll
        for (int rr = 1; rr < MS; rr <<= 1) {
            l = fmaxf(l, __shfl_xor_sync(0xffffffffu, l, rr));
            r = fmaxf(r, __shfl_xor_sync(0xffffffffu, r, rr));
        }
        #pragma unroll
        for (int d = 0; d < G; d++) {
            a0[d] = __expf(av[d] - l);
            row[2 * (G * si + d)] = __expf(bv[d] - r);
        }
        base0 = l + r;
    }
    {
        float av[G], bv[G];
        const float* h1 = hin + ((size_t)n1 * F_in + 2 * f) * 16 + G * si;
        if constexpr (G >= 4) {
            #pragma unroll
            for (int c = 0; c < G / 4; c++) {
                ((float4*)av)[c] = *(const float4*)(h1 + 4 * c);
                ((float4*)bv)[c] = *(const float4*)(h1 + 16 + 4 * c);
            }
        } else {
            ((float2*)av)[0] = *(const float2*)(h1);
            ((float2*)bv)[0] = *(const float2*)(h1 + 16);
        }
        float l = av[0], r = bv[0];
        #pragma unroll
        for (int d = 1; d < G; d++) { l = fmaxf(l, av[d]); r = fmaxf(r, bv[d]); }
        #pragma unroll
        for (int rr = 1; rr < MS; rr <<= 1) {
            l = fmaxf(l, __shfl_xor_sync(0xffffffffu, l, rr));
            r = fmaxf(r, __shfl_xor_sync(0xffffffffu, r, rr));
        }
        #pragma unroll
        for (int d = 0; d < G; d++) {
            a1[d] = __expf(av[d] - l);
            row[2 * (G * si + d) + 1] = __expf(bv[d] - r);
        }
        base1 = l + r;
    }
    __syncthreads();

    // ---- Mainloop -------------------------------------------------------
    u64 acc0[8], acc1[8];
    #pragma unroll
    for (int u = 0; u < 8; u++) { acc0[u] = 0ull; acc1[u] = 0ull; }

    const float* pq0 = Ssm + si * (G * 256) + 4 * (0 ^ xr);
    const float* pq1 = Ssm + si * (G * 256) + 4 * (1 ^ xr);
    const float* pq2 = Ssm + si * (G * 256) + 4 * (2 ^ xr);
    const float* pq3 = Ssm + si * (G * 256) + 4 * (3 ^ xr);
    const u64* rowq = (const u64*)row;

    #pragma unroll UJ
    for (int j = 0; j < 16; j++) {
        float b0, b1;
        unpack2(rowq[j], b0, b1);
        const int jo = j * 16;
        #pragma unroll
        for (int d = 0; d < G; d++) {
            const int o = d * 256 + jo;
            const u64 p0 = pack2(a0[d] * b0);
            const u64 p1 = pack2(a1[d] * b1);
            ulonglong2 w;
            w = *(const ulonglong2*)(pq0 + o);
            fma2(acc0[0], p0, w.x); fma2(acc0[1], p0, w.y);
            fma2(acc1[0], p1, w.x); fma2(acc1[1], p1, w.y);
            w = *(const ulonglong2*)(pq1 + o);
            fma2(acc0[2], p0, w.x); fma2(acc0[3], p0, w.y);
            fma2(acc1[2], p1, w.x); fma2(acc1[3], p1, w.y);
            w = *(const ulonglong2*)(pq2 + o);
            fma2(acc0[4], p0, w.x); fma2(acc0[5], p0, w.y);
            fma2(acc1[4], p1, w.x); fma2(acc1[5], p1, w.y);
            w = *(const ulonglong2*)(pq3 + o);
            fma2(acc0[6], p0, w.x); fma2(acc0[7], p0, w.y);
            fma2(acc1[6], p1, w.x); fma2(acc1[7], p1, w.y);
        }
    }

    // ---- Reduce across si lanes -----------------------------------------
    if constexpr (MS >= 2) {
        u64 t0[8], t1[8];
        #pragma unroll
        for (int u = 0; u < 8; u++) {
            t0[u] = __shfl_xor_sync(0xffffffffu, acc0[u ^ 2], 1);
            t1[u] = __shfl_xor_sync(0xffffffffu, acc1[u ^ 2], 1);
        }
        #pragma unroll
        for (int u = 0; u < 8; u++) { acc0[u] = add2(acc0[u], t0[u]); acc1[u] = add2(acc1[u], t1[u]); }
    }
    if constexpr (MS >= 4) {
        u64 t0[8], t1[8];
        #pragma unroll
        for (int u = 0; u < 8; u++) {
            t0[u] = __shfl_xor_sync(0xffffffffu, acc0[u ^ 4], 2);
            t1[u] = __shfl_xor_sync(0xffffffffu, acc1[u ^ 4], 2);
        }
        #pragma unroll
        for (int u = 0; u < 8; u++) { acc0[u] = add2(acc0[u], t0[u]); acc1[u] = add2(acc1[u], t1[u]); }
    }
    if constexpr (MS == 8) {
        u64 t0[8], t1[8];
        #pragma unroll
        for (int u = 0; u < 8; u++) {
            t0[u] = __shfl_xor_sync(0xffffffffu, acc0[u], 4);
            t1[u] = __shfl_xor_sync(0xffffffffu, acc1[u], 4);
        }
        #pragma unroll
        for (int u = 0; u < 8; u++) { acc0[u] = add2(acc0[u], t0[u]); acc1[u] = add2(acc1[u], t1[u]); }
    }

    // ---- Store -----------------------------------------------------------
    float* o0p = hout + ((size_t)n0 * F_out + f) * 16;
    float* o1p = hout + ((size_t)n1 * F_out + f) * 16;
    if constexpr (MS == 1) {
        #pragma unroll
        for (int qq = 0; qq < 4; qq++) {
            store_quad(o0p + 4 * qq, acc0[2 * qq], acc0[2 * qq + 1], base0);
            store_quad(o1p + 4 * qq, acc1[2 * qq], acc1[2 * qq + 1], base1);
        }
    } else if constexpr (MS == 2) {
        const int ka = si ? 12 : 0, kb = si ? 8 : 4;
        u64 A0 = si ? acc0[4] : acc0[0], A1 = si ? acc0[5] : acc0[1];
        u64 B0 = si ? acc0[6] : acc0[2], B1 = si ? acc0[7] : acc0[3];
        store_quad(o0p + ka, A0, A1, base0);
        store_quad(o0p + kb, B0, B1, base0);
        u64 C0 = si ? acc1[4] : acc1[0], C1 = si ? acc1[5] : acc1[1];
        u64 D0 = si ? acc1[6] : acc1[2], D1 = si ? acc1[7] : acc1[3];
        store_quad(o1p + ka, C0, C1, base1);
        store_quad(o1p + kb, D0, D1, base1);
    } else if constexpr (MS == 4) {
        store_quad(o0p + 4 * si, acc0[0], acc0[1], base0);
        store_quad(o1p + 4 * si, acc1[0], acc1[1], base1);
    } else { // MS == 8
        if (si < 4) {
            store_quad(o0p + 4 * si, acc0[0], acc0[1], base0);
            store_quad(o1p + 4 * si, acc1[0], acc1[1], base1);
        }
    }
}

// Wrapper A: R11-exact launch bounds (no min-blocks) — L2/L3/L4.
template<int MS>
__global__ void __launch_bounds__(128) layer_plain(
    const float* __restrict__ hin, const float* __restrict__ Wl,
    float* __restrict__ hout, int F_in)
{
    layer_body<MS>(hin, Wl, hout, F_in);
}

// Wrapper B: reg-capped for single-wave 1024-block grids — L1 (<2,7>).
template<int MS, int MINB>
__global__ void __launch_bounds__(128, MINB) layer_capped(
    const float* __restrict__ hin, const float* __restrict__ Wl,
    float* __restrict__ hout, int F_in)
{
    layer_body<MS>(hin, Wl, hout, F_in);
}

// ---------------------------------------------------------------------------
// Root — widened (R16): 128 blocks x 128 threads, one n per warp.
// ---------------------------------------------------------------------------
__global__ void __launch_bounds__(128) root_kernel(
    const float* __restrict__ h4, const float* __restrict__ Wroot,
    float* __restrict__ out)
{
    const int tid  = threadIdx.x;
    const int wid  = tid >> 5;
    const int t    = tid & 31;
    const int n    = blockIdx.x * 4 + wid;
    const float4* hp = (const float4*)(h4 + (size_t)n * 512);

    float4 a = make_float4(0.f, 0.f, 0.f, 0.f);
    #pragma unroll
    for (int r = 0; r < 4; r++) {
        float4 q = hp[t + 32 * r];
        a.x += q.x; a.y += q.y; a.z += q.z; a.w += q.w;
    }
    #pragma unroll
    for (int st = 4; st <= 16; st <<= 1) {
        a.x += __shfl_xor_sync(0xffffffffu, a.x, st);
        a.y += __shfl_xor_sync(0xffffffffu, a.y, st);
        a.z += __shfl_xor_sync(0xffffffffu, a.z, st);
        a.w += __shfl_xor_sync(0xffffffffu, a.w, st);
    }
    __shared__ float sred[4][16];
    if (t < 4) {
        sred[wid][4*t]   = a.x; sred[wid][4*t+1] = a.y;
        sred[wid][4*t+2] = a.z; sred[wid][4*t+3] = a.w;
    }
    __syncwarp();

    if (t == 0) {
        float w[16];
        #pragma unroll
        for (int k = 0; k < 16; k++) w[k] = Wroot[k];
        float wm = w[0];
        #pragma unroll
        for (int k = 1; k < 16; k++) wm = fmaxf(wm, w[k]);
        float Z = 0.f;
        #pragma unroll
        for (int k = 0; k < 16; k++) Z += __expf(w[k] - wm);
        const float lz = __logf(Z) + wm;

        float tv[16];
        float tm = -1e30f;
        #pragma unroll
        for (int k = 0; k < 16; k++) {
            tv[k] = sred[wid][k] + w[k] - lz;
            tm = fmaxf(tm, tv[k]);
        }
        float ss = 0.f;
        #pragma unroll
        for (int k = 0; k < 16; k++) ss += __expf(tv[k] - tm);
        out[n] = __logf(ss) + tm;
    }
}

// ---------------------------------------------------------------------------
extern "C" void kernel_launch(void* const* d_in, const int* in_sizes, int n_in,
                              void* d_out, int out_size)
{
    const float* x  = (const float*)d_in[0];
    const float* W1 = (const float*)d_in[1];
    const float* W2 = (const float*)d_in[2];
    const float* W3 = (const float*)d_in[3];
    const float* W4 = (const float*)d_in[4];
    const float* Wr = (const float*)d_in[5];
    float* out = (float*)d_out;

    float *hA, *hB;
    cudaGetSymbolAddress((void**)&hA, g_hA);
    cudaGetSymbolAddress((void**)&hB, g_hB);

    // smem = (4224 + NSL*34) floats; all < 48KB.
    const size_t sm2 = (4224 +  64 * 34) * 4;  // MS=2 : 25600
    const size_t sm4 = (4224 +  32 * 34) * 4;  // MS=4 : 21248
    const size_t sm8 = (4224 +  16 * 34) * 4;  // MS=8 : 19072

    // L1: capped <2,7>, 1024 blocks single wave (R15 win).
    // L2/L3/L4: plain wrappers = R11-exact codegen (76-reg class), 512 blocks.
    layer_capped<2, 7><<<dim3(256, 4), 128, sm2>>>(x,  W1, hA, 512);
    layer_plain<2>    <<<dim3(128, 4), 128, sm2>>>(hA, W2, hB, 256);
    layer_plain<4>    <<<dim3(64, 8),  128, sm4>>>(hB, W3, hA, 128);
    layer_plain<8>    <<<dim3(32, 16), 128, sm8>>>(hA, W4, hB, 64);

    root_kernel<<<128, 128>>>(hB, Wr, out);
}